// round 2
// baseline (speedup 1.0000x reference)
#include <cuda_runtime.h>
#include <cuda_bf16.h>

// Problem constants (shapes are fixed by the dataset)
#define NN   50000
#define EE   800000
#define HH   128       // hidden / output channels (both layers)
#define FIN  256
#define EDIM 60
#define NEG_SLOPE 0.2f

// ------------------------- scratch (static device globals; no allocation) ---
__device__ float g_h[(size_t)NN * HH];     // h = A @ W  (per layer)
__device__ float g_out[(size_t)NN * HH];   // aggregated layer output / GEMM input / z
__device__ float g_ae[EE];                 // per-edge alpha_e
__device__ int   g_col[EE];                // CSR: edge ids grouped by dst
__device__ int   g_deg[NN];
__device__ int   g_cursor[NN];
__device__ int   g_rowptr[NN + 1];
__device__ float g_as[NN];                 // alpha_src per node
__device__ float g_ad[NN];                 // alpha_dst per node
__device__ float g_sumae[NN];              // sum of incoming alpha_e (for self loop)
__device__ float g_wE1[EDIM];              // We1 @ a_edge1
__device__ float g_wE2[EDIM];              // We2 @ a_edge2

// ------------------------- helpers ------------------------------------------
__device__ __forceinline__ float warpSum(float v) {
#pragma unroll
    for (int o = 16; o; o >>= 1) v += __shfl_xor_sync(0xffffffffu, v, o);
    return v;
}
__device__ __forceinline__ float warpMax(float v) {
#pragma unroll
    for (int o = 16; o; o >>= 1) v = fmaxf(v, __shfl_xor_sync(0xffffffffu, v, o));
    return v;
}
__device__ __forceinline__ float lrelu(float a) {
    return a > 0.f ? a : NEG_SLOPE * a;
}

// ------------------------- CSR build -----------------------------------------
__global__ void k_zero_csr(int n) {
    int i = blockIdx.x * blockDim.x + threadIdx.x;
    if (i < n) { g_deg[i] = 0; g_cursor[i] = 0; }
}
__global__ void k_deg(const int* __restrict__ dst, int E) {
    int i = blockIdx.x * blockDim.x + threadIdx.x;
    if (i < E) atomicAdd(&g_deg[dst[i]], 1);
}
// single-block inclusive scan -> exclusive rowptr
__global__ void k_scan(int n) {
    __shared__ int sm[1024];
    __shared__ int carry;
    int tid = threadIdx.x;
    if (tid == 0) { carry = 0; g_rowptr[0] = 0; }
    __syncthreads();
    for (int base = 0; base < n; base += 1024) {
        int i = base + tid;
        int v = (i < n) ? g_deg[i] : 0;
        sm[tid] = v;
        __syncthreads();
        for (int off = 1; off < 1024; off <<= 1) {
            int t = (tid >= off) ? sm[tid - off] : 0;
            __syncthreads();
            sm[tid] += t;
            __syncthreads();
        }
        if (i < n) g_rowptr[i + 1] = carry + sm[tid];
        __syncthreads();
        if (tid == 1023) carry += sm[1023];
        __syncthreads();
    }
}
__global__ void k_fill(const int* __restrict__ dst, int E) {
    int i = blockIdx.x * blockDim.x + threadIdx.x;
    if (i < E) {
        int d = dst[i];
        int pos = atomicAdd(&g_cursor[d], 1);
        g_col[g_rowptr[d] + pos] = i;
    }
}

// ------------------------- wE = We @ a_edge ----------------------------------
__global__ void k_we(const float* __restrict__ We, const float* __restrict__ ae,
                     int which) {
    int warp = (blockIdx.x * blockDim.x + threadIdx.x) >> 5;
    int lane = threadIdx.x & 31;
    if (warp >= EDIM) return;
    float p = 0.f;
    for (int k = lane; k < HH; k += 32) p += We[warp * HH + k] * ae[k];
    p = warpSum(p);
    if (lane == 0) {
        if (which == 0) g_wE1[warp] = p; else g_wE2[warp] = p;
    }
}

// ------------------------- SGEMM: C[M,128] = A[M,K] @ B[K,128] ---------------
// BM=128, BN=128, BK=16, 256 threads, 8x8 per thread
__global__ __launch_bounds__(256, 2)
void k_sgemm(const float* __restrict__ Aext, const float* __restrict__ B,
             int M, int K, int a_from_gout) {
    __shared__ float As[16][132];   // transposed, padded
    __shared__ float Bs[16][128];
    const float* A = a_from_gout ? g_out : Aext;
    int block_row = blockIdx.x * 128;
    int tid = threadIdx.x;
    int tcol = (tid & 15) * 8;
    int trow = (tid >> 4) * 8;
    float acc[8][8];
#pragma unroll
    for (int i = 0; i < 8; i++)
#pragma unroll
        for (int j = 0; j < 8; j++) acc[i][j] = 0.f;

    for (int k0 = 0; k0 < K; k0 += 16) {
        // load A tile 128x16 (as float4), store transposed
#pragma unroll
        for (int t = tid; t < 512; t += 256) {
            int m = t >> 2;
            int kq = (t & 3) * 4;
            int gr = block_row + m;
            float4 v = make_float4(0.f, 0.f, 0.f, 0.f);
            if (gr < M) v = *(const float4*)(A + (size_t)gr * K + k0 + kq);
            As[kq + 0][m] = v.x; As[kq + 1][m] = v.y;
            As[kq + 2][m] = v.z; As[kq + 3][m] = v.w;
        }
        // load B tile 16x128
#pragma unroll
        for (int t = tid; t < 512; t += 256) {
            int kr = t >> 5;
            int nq = (t & 31) * 4;
            *(float4*)&Bs[kr][nq] = *(const float4*)(B + (size_t)(k0 + kr) * 128 + nq);
        }
        __syncthreads();
#pragma unroll
        for (int kk = 0; kk < 16; kk++) {
            float a[8], b[8];
#pragma unroll
            for (int i = 0; i < 8; i++) a[i] = As[kk][trow + i];
#pragma unroll
            for (int j = 0; j < 8; j++) b[j] = Bs[kk][tcol + j];
#pragma unroll
            for (int i = 0; i < 8; i++)
#pragma unroll
                for (int j = 0; j < 8; j++) acc[i][j] += a[i] * b[j];
        }
        __syncthreads();
    }
#pragma unroll
    for (int i = 0; i < 8; i++) {
        int gr = block_row + trow + i;
        if (gr < M) {
            float4 v0 = make_float4(acc[i][0], acc[i][1], acc[i][2], acc[i][3]);
            float4 v1 = make_float4(acc[i][4], acc[i][5], acc[i][6], acc[i][7]);
            *(float4*)(g_h + (size_t)gr * 128 + tcol) = v0;
            *(float4*)(g_h + (size_t)gr * 128 + tcol + 4) = v1;
        }
    }
}

// ------------------------- per-node attention dots ---------------------------
__global__ void k_attdots(const float* __restrict__ a_src,
                          const float* __restrict__ a_dst, int n) {
    int warp = (blockIdx.x * blockDim.x + threadIdx.x) >> 5;
    int lane = threadIdx.x & 31;
    if (warp >= n) return;
    float4 hv = ((const float4*)(g_h + (size_t)warp * HH))[lane];
    float4 s4 = ((const float4*)a_src)[lane];
    float4 d4 = ((const float4*)a_dst)[lane];
    float ps = hv.x * s4.x + hv.y * s4.y + hv.z * s4.z + hv.w * s4.w;
    float pd = hv.x * d4.x + hv.y * d4.y + hv.z * d4.z + hv.w * d4.w;
    ps = warpSum(ps);
    pd = warpSum(pd);
    if (lane == 0) { g_as[warp] = ps; g_ad[warp] = pd; }
}

__global__ void k_zero_sumae(int n) {
    int i = blockIdx.x * blockDim.x + threadIdx.x;
    if (i < n) g_sumae[i] = 0.f;
}

// ------------------------- per-edge alpha_e ----------------------------------
__global__ void k_edge_ae(const float* __restrict__ ef,
                          const int* __restrict__ dst, int E, int which) {
    int gid = blockIdx.x * blockDim.x + threadIdx.x;
    int e = gid >> 3;
    int sub = gid & 7;
    if (e >= E) return;
    const float* wE = which == 0 ? g_wE1 : g_wE2;
    const float* row = ef + (size_t)e * EDIM;
    float p = 0.f;
    for (int j = sub; j < EDIM; j += 8) p += row[j] * wE[j];
    p += __shfl_xor_sync(0xffffffffu, p, 4);
    p += __shfl_xor_sync(0xffffffffu, p, 2);
    p += __shfl_xor_sync(0xffffffffu, p, 1);
    if (sub == 0) {
        g_ae[e] = p;
        atomicAdd(&g_sumae[dst[e]], p);
    }
}

// ------------------------- fused softmax + aggregate (warp per node) ---------
__global__ __launch_bounds__(256)
void k_aggregate(const int* __restrict__ src, const float* __restrict__ bias,
                 int n, int relu_flag) {
    int warp = (blockIdx.x * blockDim.x + threadIdx.x) >> 5;
    int lane = threadIdx.x & 31;
    if (warp >= n) return;
    int v = warp;
    int r0 = g_rowptr[v], r1 = g_rowptr[v + 1];
    int deg = r1 - r0;
    float adv = g_ad[v];
    float aloop = lrelu(g_as[v] + adv + g_sumae[v] / (float)(deg > 0 ? deg : 1));

    // pass 1: running max (self-loop included)
    float m = aloop;
    for (int i = r0 + lane; i < r1; i += 32) {
        int e = g_col[i];
        float a = lrelu(g_as[src[e]] + adv + g_ae[e]);
        m = fmaxf(m, a);
    }
    m = warpMax(m);

    // pass 2: unnormalized weighted sum + denom
    float4 acc = make_float4(0.f, 0.f, 0.f, 0.f);
    float dsum = 0.f;
    for (int c0 = r0; c0 < r1; c0 += 32) {
        int i = c0 + lane;
        float w = 0.f;
        int s = 0;
        if (i < r1) {
            int e = g_col[i];
            s = src[e];
            float a = lrelu(g_as[s] + adv + g_ae[e]);
            w = __expf(a - m);
        }
        dsum += w;
        int cnt = min(32, r1 - c0);
        for (int j = 0; j < cnt; j++) {
            float wj = __shfl_sync(0xffffffffu, w, j);
            int sj = __shfl_sync(0xffffffffu, s, j);
            float4 hv = ((const float4*)(g_h + (size_t)sj * HH))[lane];
            acc.x += wj * hv.x; acc.y += wj * hv.y;
            acc.z += wj * hv.z; acc.w += wj * hv.w;
        }
    }
    // self loop
    float wl = __expf(aloop - m);
    {
        float4 hv = ((const float4*)(g_h + (size_t)v * HH))[lane];
        acc.x += wl * hv.x; acc.y += wl * hv.y;
        acc.z += wl * hv.z; acc.w += wl * hv.w;
    }
    float denom = warpSum(dsum) + wl;
    float inv = 1.f / denom;
    float4 b4 = ((const float4*)bias)[lane];
    float4 o;
    o.x = acc.x * inv + b4.x;
    o.y = acc.y * inv + b4.y;
    o.z = acc.z * inv + b4.z;
    o.w = acc.w * inv + b4.w;
    if (relu_flag) {
        o.x = fmaxf(o.x, 0.f); o.y = fmaxf(o.y, 0.f);
        o.z = fmaxf(o.z, 0.f); o.w = fmaxf(o.w, 0.f);
    }
    ((float4*)(g_out + (size_t)v * HH))[lane] = o;
}

// ------------------------- decode: out[i] = z[s_i].z[d_i] + z[s_{i+h}].z[d_{i+h}]
__global__ __launch_bounds__(256)
void k_decode(const int* __restrict__ src, const int* __restrict__ dst,
              float* __restrict__ out, int half) {
    int warp = (blockIdx.x * blockDim.x + threadIdx.x) >> 5;
    int lane = threadIdx.x & 31;
    if (warp >= half) return;
    int s1 = src[warp], d1 = dst[warp];
    int s2 = src[warp + half], d2 = dst[warp + half];
    float4 a = ((const float4*)(g_out + (size_t)s1 * HH))[lane];
    float4 b = ((const float4*)(g_out + (size_t)d1 * HH))[lane];
    float4 c = ((const float4*)(g_out + (size_t)s2 * HH))[lane];
    float4 d = ((const float4*)(g_out + (size_t)d2 * HH))[lane];
    float p = a.x * b.x + a.y * b.y + a.z * b.z + a.w * b.w
            + c.x * d.x + c.y * d.y + c.z * d.z + c.w * d.w;
    p = warpSum(p);
    if (lane == 0) out[warp] = p;
}

// ------------------------- launch --------------------------------------------
extern "C" void kernel_launch(void* const* d_in, const int* in_sizes, int n_in,
                              void* d_out, int out_size) {
    const float* x   = (const float*)d_in[0];
    const int*   ei  = (const int*)d_in[1];
    const float* ef  = (const float*)d_in[2];
    const float* W1  = (const float*)d_in[4];
    const float* as1 = (const float*)d_in[5];
    const float* ad1 = (const float*)d_in[6];
    const float* We1 = (const float*)d_in[7];
    const float* ae1 = (const float*)d_in[8];
    const float* b1  = (const float*)d_in[9];
    const float* W2  = (const float*)d_in[10];
    const float* as2 = (const float*)d_in[11];
    const float* ad2 = (const float*)d_in[12];
    const float* We2 = (const float*)d_in[13];
    const float* ae2 = (const float*)d_in[14];
    const float* b2  = (const float*)d_in[15];

    const int E = in_sizes[1] / 2;
    const int N = in_sizes[0] / FIN;
    const int* src = ei;
    const int* dst = ei + E;

    // CSR build (shared across both layers)
    k_zero_csr<<<(N + 255) / 256, 256>>>(N);
    k_deg<<<(E + 255) / 256, 256>>>(dst, E);
    k_scan<<<1, 1024>>>(N);
    k_fill<<<(E + 255) / 256, 256>>>(dst, E);

    // wE vectors
    k_we<<<2, 1024>>>(We1, ae1, 0);
    k_we<<<2, 1024>>>(We2, ae2, 1);

    // ---------------- layer 1 ----------------
    k_sgemm<<<(N + 127) / 128, 256>>>(x, W1, N, FIN, 0);
    k_attdots<<<(N * 32 + 255) / 256, 256>>>(as1, ad1, N);
    k_zero_sumae<<<(N + 255) / 256, 256>>>(N);
    k_edge_ae<<<(E * 8 + 255) / 256, 256>>>(ef, dst, E, 0);
    k_aggregate<<<(N * 32 + 255) / 256, 256>>>(src, b1, N, 1);

    // ---------------- layer 2 ----------------
    k_sgemm<<<(N + 127) / 128, 256>>>(nullptr, W2, N, HH, 1);
    k_attdots<<<(N * 32 + 255) / 256, 256>>>(as2, ad2, N);
    k_zero_sumae<<<(N + 255) / 256, 256>>>(N);
    k_edge_ae<<<(E * 8 + 255) / 256, 256>>>(ef, dst, E, 1);
    k_aggregate<<<(N * 32 + 255) / 256, 256>>>(src, b2, N, 0);

    // ---------------- decode ----------------
    int half = E / 2;
    k_decode<<<((size_t)half * 32 + 255) / 256, 256>>>(src, dst, (float*)d_out, half);
}

// round 4
// speedup vs baseline: 1.1906x; 1.1906x over previous
#include <cuda_runtime.h>
#include <cuda_bf16.h>

// Problem constants (shapes fixed by dataset)
#define NN   50000
#define EE   800000
#define HH   128
#define FIN  256
#define EDIM 60
#define NEG_SLOPE 0.2f

// ------------------------- scratch ------------------------------------------
__device__ float g_h[(size_t)NN * HH];
__device__ float g_out[(size_t)NN * HH];
__device__ float g_ae1a[EE];
__device__ float g_ae2a[EE];
__device__ float g_res[EE];
__device__ int   g_col[EE];
__device__ int   g_deg[NN];
__device__ int   g_cursor[NN];
__device__ int   g_rowptr[NN + 1];
__device__ float g_as[NN];
__device__ float g_ad[NN];
__device__ float g_sumae1[NN];
__device__ float g_sumae2[NN];
__device__ float g_wE1[EDIM];
__device__ float g_wE2[EDIM];

// ------------------------- helpers ------------------------------------------
__device__ __forceinline__ float warpSum(float v) {
#pragma unroll
    for (int o = 16; o; o >>= 1) v += __shfl_xor_sync(0xffffffffu, v, o);
    return v;
}
__device__ __forceinline__ float warpMax(float v) {
#pragma unroll
    for (int o = 16; o; o >>= 1) v = fmaxf(v, __shfl_xor_sync(0xffffffffu, v, o));
    return v;
}
__device__ __forceinline__ float lrelu(float a) { return a > 0.f ? a : NEG_SLOPE * a; }

// packed fp32x2 (Blackwell): double-rate fp32 FMA
__device__ __forceinline__ void ffma2(unsigned long long& d, unsigned long long a,
                                      unsigned long long b) {
    asm("fma.rn.f32x2 %0, %1, %2, %0;" : "+l"(d) : "l"(a), "l"(b));
}
__device__ __forceinline__ unsigned long long dup2(float x) {
    unsigned long long r;
    asm("mov.b64 %0, {%1, %1};" : "=l"(r) : "f"(x));
    return r;
}
__device__ __forceinline__ void unpack2(unsigned long long v, float& lo, float& hi) {
    asm("mov.b64 {%0, %1}, %2;" : "=f"(lo), "=f"(hi) : "l"(v));
}

// ------------------------- CSR build ----------------------------------------
__global__ void k_zero(int n) {
    int i = blockIdx.x * blockDim.x + threadIdx.x;
    if (i < n) { g_deg[i] = 0; g_cursor[i] = 0; g_sumae1[i] = 0.f; g_sumae2[i] = 0.f; }
}
__global__ void k_deg(const int* __restrict__ dst, int E) {
    int i = blockIdx.x * blockDim.x + threadIdx.x;
    if (i < E) atomicAdd(&g_deg[dst[i]], 1);
}
__global__ void k_scan(int n) {
    __shared__ int sm[1024];
    __shared__ int carry;
    int tid = threadIdx.x;
    if (tid == 0) { carry = 0; g_rowptr[0] = 0; }
    __syncthreads();
    for (int base = 0; base < n; base += 1024) {
        int i = base + tid;
        int v = (i < n) ? g_deg[i] : 0;
        sm[tid] = v;
        __syncthreads();
        for (int off = 1; off < 1024; off <<= 1) {
            int t = (tid >= off) ? sm[tid - off] : 0;
            __syncthreads();
            sm[tid] += t;
            __syncthreads();
        }
        if (i < n) g_rowptr[i + 1] = carry + sm[tid];
        __syncthreads();
        if (tid == 1023) carry += sm[1023];
        __syncthreads();
    }
}
__global__ void k_fill(const int* __restrict__ dst, int E) {
    int i = blockIdx.x * blockDim.x + threadIdx.x;
    if (i < E) {
        int d = dst[i];
        int pos = atomicAdd(&g_cursor[d], 1);
        g_col[g_rowptr[d] + pos] = i;
    }
}

// ------------------------- wE = We @ a_edge (both layers) --------------------
__global__ void k_we2(const float* __restrict__ We1, const float* __restrict__ ae1,
                      const float* __restrict__ We2, const float* __restrict__ ae2) {
    int warp = (blockIdx.x * blockDim.x + threadIdx.x) >> 5;
    int lane = threadIdx.x & 31;
    if (warp >= 2 * EDIM) return;
    int which = warp >= EDIM;
    int r = warp - which * EDIM;
    const float* We = which ? We2 : We1;
    const float* ae = which ? ae2 : ae1;
    float p = 0.f;
    for (int k = lane; k < HH; k += 32) p += We[r * HH + k] * ae[k];
    p = warpSum(p);
    if (lane == 0) { if (which) g_wE2[r] = p; else g_wE1[r] = p; }
}

// ------------------------- per-edge alpha_e (both layers, one ef pass) -------
__global__ void k_edge_ae(const float* __restrict__ ef, const int* __restrict__ dst, int E) {
    int gid = blockIdx.x * blockDim.x + threadIdx.x;
    int e = gid >> 3;
    int sub = gid & 7;
    if (e >= E) return;
    const float* row = ef + (size_t)e * EDIM;
    float p1 = 0.f, p2 = 0.f;
    for (int j = sub; j < EDIM; j += 8) {
        float v = row[j];
        p1 += v * g_wE1[j];
        p2 += v * g_wE2[j];
    }
#pragma unroll
    for (int o = 4; o; o >>= 1) {
        p1 += __shfl_xor_sync(0xffffffffu, p1, o);
        p2 += __shfl_xor_sync(0xffffffffu, p2, o);
    }
    if (sub == 0) {
        g_ae1a[e] = p1;
        g_ae2a[e] = p2;
        int d = dst[e];
        atomicAdd(&g_sumae1[d], p1);
        atomicAdd(&g_sumae2[d], p2);
    }
}

// ------------------------- SGEMM + fused attention dots ----------------------
// C[M,128] = A[M,K] @ B[K,128]; BM=128, BN=128, BK=8, 256 threads, 8x8/thread,
// f32x2 packed accumulators (rows paired), double-buffered smem, 1 sync/iter.
// Epilogue also computes g_as[r] = C[r,:]·avs, g_ad[r] = C[r,:]·avd.
#define BK 8
__global__ __launch_bounds__(256, 2)
void k_sgemm(const float* __restrict__ Aext, const float* __restrict__ B,
             const float* __restrict__ avs, const float* __restrict__ avd,
             int M, int K, int a_from_gout) {
    __shared__ float As[2][BK][128];
    __shared__ float Bs[2][BK][128];
    const float* A = a_from_gout ? g_out : Aext;
    const int tid = threadIdx.x;
    const int block_row = blockIdx.x * 128;
    const int trow = (tid >> 4) * 8;
    const int tcol = (tid & 15) * 8;
    // A stage: row ar (0..127), cols ac..ac+3
    const int ar = tid >> 1;
    const int ac = (tid & 1) * 4;
    // B stage: row br (0..7), cols bc..bc+3
    const int br = tid >> 5;
    const int bc = (tid & 31) * 4;

    float4 areg, breg;
    unsigned long long acc[4][8];
#pragma unroll
    for (int i = 0; i < 4; i++)
#pragma unroll
        for (int j = 0; j < 8; j++) acc[i][j] = 0ull;

    const int gr = block_row + ar;
    // preload tile 0
    if (gr < M) areg = *(const float4*)(A + (size_t)gr * K + ac);
    else areg = make_float4(0.f, 0.f, 0.f, 0.f);
    breg = *(const float4*)(B + (size_t)br * 128 + bc);
    As[0][ac + 0][ar] = areg.x; As[0][ac + 1][ar] = areg.y;
    As[0][ac + 2][ar] = areg.z; As[0][ac + 3][ar] = areg.w;
    *(float4*)&Bs[0][br][bc] = breg;
    __syncthreads();

    const int nt = K / BK;
    for (int t = 0; t < nt; t++) {
        int cur = t & 1;
        if (t + 1 < nt) {
            int k0 = (t + 1) * BK;
            if (gr < M) areg = *(const float4*)(A + (size_t)gr * K + k0 + ac);
            else areg = make_float4(0.f, 0.f, 0.f, 0.f);
            breg = *(const float4*)(B + (size_t)(k0 + br) * 128 + bc);
        }
#pragma unroll
        for (int kk = 0; kk < BK; kk++) {
            const ulonglong2* ap = (const ulonglong2*)&As[cur][kk][trow];
            ulonglong2 aa = ap[0], ab = ap[1];
            unsigned long long a2[4] = {aa.x, aa.y, ab.x, ab.y};
            float4 b0 = *(const float4*)&Bs[cur][kk][tcol];
            float4 b1 = *(const float4*)&Bs[cur][kk][tcol + 4];
            unsigned long long b2[8];
            b2[0] = dup2(b0.x); b2[1] = dup2(b0.y); b2[2] = dup2(b0.z); b2[3] = dup2(b0.w);
            b2[4] = dup2(b1.x); b2[5] = dup2(b1.y); b2[6] = dup2(b1.z); b2[7] = dup2(b1.w);
#pragma unroll
            for (int i2 = 0; i2 < 4; i2++)
#pragma unroll
                for (int j = 0; j < 8; j++) ffma2(acc[i2][j], a2[i2], b2[j]);
        }
        if (t + 1 < nt) {
            int nxt = cur ^ 1;
            As[nxt][ac + 0][ar] = areg.x; As[nxt][ac + 1][ar] = areg.y;
            As[nxt][ac + 2][ar] = areg.z; As[nxt][ac + 3][ar] = areg.w;
            *(float4*)&Bs[nxt][br][bc] = breg;
        }
        __syncthreads();
    }

    // epilogue: store rows + fused attention dots
    float4 s0 = *(const float4*)(avs + tcol);
    float4 s1 = *(const float4*)(avs + tcol + 4);
    float4 d0 = *(const float4*)(avd + tcol);
    float4 d1 = *(const float4*)(avd + tcol + 4);
#pragma unroll
    for (int i2 = 0; i2 < 4; i2++) {
        float lo[8], hi[8];
#pragma unroll
        for (int j = 0; j < 8; j++) unpack2(acc[i2][j], lo[j], hi[j]);
#pragma unroll
        for (int h = 0; h < 2; h++) {
            float* rowv = h ? hi : lo;
            int r = block_row + trow + 2 * i2 + h;
            float ps = rowv[0] * s0.x + rowv[1] * s0.y + rowv[2] * s0.z + rowv[3] * s0.w
                     + rowv[4] * s1.x + rowv[5] * s1.y + rowv[6] * s1.z + rowv[7] * s1.w;
            float pd = rowv[0] * d0.x + rowv[1] * d0.y + rowv[2] * d0.z + rowv[3] * d0.w
                     + rowv[4] * d1.x + rowv[5] * d1.y + rowv[6] * d1.z + rowv[7] * d1.w;
#pragma unroll
            for (int o = 8; o; o >>= 1) {
                ps += __shfl_xor_sync(0xffffffffu, ps, o);
                pd += __shfl_xor_sync(0xffffffffu, pd, o);
            }
            if (r < M) {
                float4 v0 = make_float4(rowv[0], rowv[1], rowv[2], rowv[3]);
                float4 v1 = make_float4(rowv[4], rowv[5], rowv[6], rowv[7]);
                *(float4*)(g_h + (size_t)r * 128 + tcol) = v0;
                *(float4*)(g_h + (size_t)r * 128 + tcol + 4) = v1;
                if ((tid & 15) == 0) { g_as[r] = ps; g_ad[r] = pd; }
            }
        }
    }
}

// ------------------------- fused softmax + aggregate (warp per node) ---------
__global__ __launch_bounds__(256)
void k_aggregate(const int* __restrict__ src, const float* __restrict__ bias,
                 int n, int layer2) {
    int warp = (blockIdx.x * blockDim.x + threadIdx.x) >> 5;
    int lane = threadIdx.x & 31;
    if (warp >= n) return;
    const float* ae   = layer2 ? g_ae2a  : g_ae1a;
    const float* sumA = layer2 ? g_sumae2 : g_sumae1;
    int v = warp;
    int r0 = g_rowptr[v], r1 = g_rowptr[v + 1];
    int deg = r1 - r0;
    float adv = g_ad[v];
    float aloop = lrelu(g_as[v] + adv + sumA[v] / (float)(deg > 0 ? deg : 1));

    // pass 1: max
    float m = aloop;
    for (int i = r0 + lane; i < r1; i += 32) {
        int e = g_col[i];
        m = fmaxf(m, lrelu(g_as[src[e]] + adv + ae[e]));
    }
    m = warpMax(m);

    // pass 2: unnormalized weighted sum + denom
    float4 acc = make_float4(0.f, 0.f, 0.f, 0.f);
    float dsum = 0.f;
    for (int c0 = r0; c0 < r1; c0 += 32) {
        int i = c0 + lane;
        float w = 0.f;
        int s = 0;
        if (i < r1) {
            int e = g_col[i];
            s = src[e];
            w = __expf(lrelu(g_as[s] + adv + ae[e]) - m);
        }
        dsum += w;
        int cnt = min(32, r1 - c0);
        int j = 0;
        for (; j + 4 <= cnt; j += 4) {
            float w0 = __shfl_sync(0xffffffffu, w, j);
            float w1 = __shfl_sync(0xffffffffu, w, j + 1);
            float w2 = __shfl_sync(0xffffffffu, w, j + 2);
            float w3 = __shfl_sync(0xffffffffu, w, j + 3);
            int sj0 = __shfl_sync(0xffffffffu, s, j);
            int sj1 = __shfl_sync(0xffffffffu, s, j + 1);
            int sj2 = __shfl_sync(0xffffffffu, s, j + 2);
            int sj3 = __shfl_sync(0xffffffffu, s, j + 3);
            float4 h0 = ((const float4*)(g_h + (size_t)sj0 * HH))[lane];
            float4 h1 = ((const float4*)(g_h + (size_t)sj1 * HH))[lane];
            float4 h2 = ((const float4*)(g_h + (size_t)sj2 * HH))[lane];
            float4 h3 = ((const float4*)(g_h + (size_t)sj3 * HH))[lane];
            acc.x += w0 * h0.x + w1 * h1.x + w2 * h2.x + w3 * h3.x;
            acc.y += w0 * h0.y + w1 * h1.y + w2 * h2.y + w3 * h3.y;
            acc.z += w0 * h0.z + w1 * h1.z + w2 * h2.z + w3 * h3.z;
            acc.w += w0 * h0.w + w1 * h1.w + w2 * h2.w + w3 * h3.w;
        }
        for (; j < cnt; j++) {
            float wj = __shfl_sync(0xffffffffu, w, j);
            int sj = __shfl_sync(0xffffffffu, s, j);
            float4 hv = ((const float4*)(g_h + (size_t)sj * HH))[lane];
            acc.x += wj * hv.x; acc.y += wj * hv.y;
            acc.z += wj * hv.z; acc.w += wj * hv.w;
        }
    }
    float wl = __expf(aloop - m);
    {
        float4 hv = ((const float4*)(g_h + (size_t)v * HH))[lane];
        acc.x += wl * hv.x; acc.y += wl * hv.y;
        acc.z += wl * hv.z; acc.w += wl * hv.w;
    }
    float inv = 1.f / (warpSum(dsum) + wl);
    float4 b4 = ((const float4*)bias)[lane];
    float4 o;
    o.x = acc.x * inv + b4.x; o.y = acc.y * inv + b4.y;
    o.z = acc.z * inv + b4.z; o.w = acc.w * inv + b4.w;
    if (!layer2) {
        o.x = fmaxf(o.x, 0.f); o.y = fmaxf(o.y, 0.f);
        o.z = fmaxf(o.z, 0.f); o.w = fmaxf(o.w, 0.f);
    }
    ((float4*)(g_out + (size_t)v * HH))[lane] = o;
}

// ------------------------- decode via dst-CSR --------------------------------
__global__ __launch_bounds__(256)
void k_decode_csr(const int* __restrict__ src, int n) {
    int warp = (blockIdx.x * blockDim.x + threadIdx.x) >> 5;
    int lane = threadIdx.x & 31;
    if (warp >= n) return;
    int v = warp;
    int r0 = g_rowptr[v], r1 = g_rowptr[v + 1];
    float4 zd = ((const float4*)(g_out + (size_t)v * HH))[lane];
    int i = r0;
    for (; i + 2 <= r1; i += 2) {
        int e0 = g_col[i], e1 = g_col[i + 1];
        int s0 = src[e0], s1 = src[e1];
        float4 z0 = ((const float4*)(g_out + (size_t)s0 * HH))[lane];
        float4 z1 = ((const float4*)(g_out + (size_t)s1 * HH))[lane];
        float p0 = zd.x * z0.x + zd.y * z0.y + zd.z * z0.z + zd.w * z0.w;
        float p1 = zd.x * z1.x + zd.y * z1.y + zd.z * z1.z + zd.w * z1.w;
#pragma unroll
        for (int o = 16; o; o >>= 1) {
            p0 += __shfl_xor_sync(0xffffffffu, p0, o);
            p1 += __shfl_xor_sync(0xffffffffu, p1, o);
        }
        if (lane == 0) { g_res[e0] = p0; g_res[e1] = p1; }
    }
    if (i < r1) {
        int e0 = g_col[i];
        int s0 = src[e0];
        float4 z0 = ((const float4*)(g_out + (size_t)s0 * HH))[lane];
        float p0 = zd.x * z0.x + zd.y * z0.y + zd.z * z0.z + zd.w * z0.w;
        p0 = warpSum(p0);
        if (lane == 0) g_res[e0] = p0;
    }
}

__global__ void k_fold(float* __restrict__ out, int half) {
    int i = blockIdx.x * blockDim.x + threadIdx.x;
    if (i < half) out[i] = g_res[i] + g_res[i + half];
}

// ------------------------- launch --------------------------------------------
extern "C" void kernel_launch(void* const* d_in, const int* in_sizes, int n_in,
                              void* d_out, int out_size) {
    const float* x   = (const float*)d_in[0];
    const int*   ei  = (const int*)d_in[1];
    const float* ef  = (const float*)d_in[2];
    const float* W1  = (const float*)d_in[4];
    const float* as1 = (const float*)d_in[5];
    const float* ad1 = (const float*)d_in[6];
    const float* We1 = (const float*)d_in[7];
    const float* ae1 = (const float*)d_in[8];
    const float* b1  = (const float*)d_in[9];
    const float* W2  = (const float*)d_in[10];
    const float* as2 = (const float*)d_in[11];
    const float* ad2 = (const float*)d_in[12];
    const float* We2 = (const float*)d_in[13];
    const float* ae2 = (const float*)d_in[14];
    const float* b2  = (const float*)d_in[15];

    const int E = in_sizes[1] / 2;
    const int N = in_sizes[0] / FIN;
    const int* src = ei;
    const int* dst = ei + E;

    // CSR build + edge dots
    k_zero<<<(N + 255) / 256, 256>>>(N);
    k_deg<<<(E + 255) / 256, 256>>>(dst, E);
    k_scan<<<1, 1024>>>(N);
    k_fill<<<(E + 255) / 256, 256>>>(dst, E);
    k_we2<<<(2 * EDIM * 32 + 255) / 256, 256>>>(We1, ae1, We2, ae2);
    k_edge_ae<<<((size_t)E * 8 + 255) / 256, 256>>>(ef, dst, E);

    // layer 1
    k_sgemm<<<(N + 127) / 128, 256>>>(x, W1, as1, ad1, N, FIN, 0);
    k_aggregate<<<(N * 32 + 255) / 256, 256>>>(src, b1, N, 0);

    // layer 2
    k_sgemm<<<(N + 127) / 128, 256>>>(nullptr, W2, as2, ad2, N, HH, 1);
    k_aggregate<<<(N * 32 + 255) / 256, 256>>>(src, b2, N, 1);

    // decode
    k_decode_csr<<<(N * 32 + 255) / 256, 256>>>(src, N);
    int half = E / 2;
    k_fold<<<(half + 255) / 256, 256>>>((float*)d_out, half);
}

// round 11
// speedup vs baseline: 1.5385x; 1.2922x over previous
#include <cuda_runtime.h>
#include <cuda_bf16.h>
#include <cstdint>

#define NN   50000
#define EE   800000
#define HH   128
#define FIN  256
#define EDIM 60
#define NEG_SLOPE 0.2f

// ------------------------- scratch ------------------------------------------
struct __align__(16) EdgeRec { int src; int eid; float ae1; float ae2; };

__device__ float g_h[(size_t)NN * HH];
__device__ float g_out[(size_t)NN * HH];
__device__ float g_ae1a[EE];
__device__ float g_ae2a[EE];
__device__ float g_res[EE];
__device__ EdgeRec g_rec[EE];
__device__ int   g_deg[NN];
__device__ int   g_cursor[NN];
__device__ int   g_rowptr[NN + 1];
__device__ float g_as[NN];
__device__ float g_ad[NN];
__device__ float g_sumae1[NN];
__device__ float g_sumae2[NN];
__device__ float g_wE1[EDIM];
__device__ float g_wE2[EDIM];
// bf16 split operands (A row-major [M][K]; B as Wt[n][k], n=out col)
__device__ __nv_bfloat16 g_Ah[(size_t)NN * FIN];
__device__ __nv_bfloat16 g_Am[(size_t)NN * FIN];
__device__ __nv_bfloat16 g_Bh[128 * FIN];
__device__ __nv_bfloat16 g_Bm[128 * FIN];

// ------------------------- helpers ------------------------------------------
__device__ __forceinline__ float warpSum(float v) {
#pragma unroll
    for (int o = 16; o; o >>= 1) v += __shfl_xor_sync(0xffffffffu, v, o);
    return v;
}
__device__ __forceinline__ float warpMax(float v) {
#pragma unroll
    for (int o = 16; o; o >>= 1) v = fmaxf(v, __shfl_xor_sync(0xffffffffu, v, o));
    return v;
}
__device__ __forceinline__ float lrelu(float a) { return a > 0.f ? a : NEG_SLOPE * a; }

__device__ __forceinline__ uint32_t smem_u32(const void* p) {
    uint32_t a;
    asm("{ .reg .u64 t; cvta.to.shared.u64 t, %1; cvt.u32.u64 %0, t; }" : "=r"(a) : "l"(p));
    return a;
}
__device__ __forceinline__ void cp16(uint32_t dsm, const void* src) {
    asm volatile("cp.async.cg.shared.global [%0], [%1], 16;"
                 :: "r"(dsm), "l"(src) : "memory");
}
#define CP_COMMIT() asm volatile("cp.async.commit_group;" ::: "memory")
#define CP_WAIT0()  asm volatile("cp.async.wait_group 0;" ::: "memory")

// mma.sync m16n8k16 bf16 (baseline PTX, valid at compute_103)
__device__ __forceinline__ void mma_bf16(float* c, const uint32_t* a, const uint32_t* b) {
    asm volatile(
        "mma.sync.aligned.m16n8k16.row.col.f32.bf16.bf16.f32 "
        "{%0,%1,%2,%3}, {%4,%5,%6,%7}, {%8,%9}, {%0,%1,%2,%3};"
        : "+f"(c[0]), "+f"(c[1]), "+f"(c[2]), "+f"(c[3])
        : "r"(a[0]), "r"(a[1]), "r"(a[2]), "r"(a[3]), "r"(b[0]), "r"(b[1]));
}

// ------------------------- CSR build ----------------------------------------
__global__ void k_zero(int n) {
    int i = blockIdx.x * blockDim.x + threadIdx.x;
    if (i < n) { g_deg[i] = 0; g_cursor[i] = 0; g_sumae1[i] = 0.f; g_sumae2[i] = 0.f; }
}

// thread-sequential-segment scan, one block
__global__ void k_scan(int n) {
    __shared__ int sm[1024];
    int tid = threadIdx.x;
    const int seg = (n + 1023) / 1024;
    int base = tid * seg;
    int s = 0;
    for (int j = 0; j < seg; j++) { int i = base + j; if (i < n) s += g_deg[i]; }
    sm[tid] = s;
    __syncthreads();
    for (int off = 1; off < 1024; off <<= 1) {
        int t = (tid >= off) ? sm[tid - off] : 0;
        __syncthreads();
        sm[tid] += t;
        __syncthreads();
    }
    int run = sm[tid] - s;   // exclusive prefix
    if (tid == 0) g_rowptr[0] = 0;
    for (int j = 0; j < seg; j++) {
        int i = base + j;
        if (i < n) { run += g_deg[i]; g_rowptr[i + 1] = run; }
    }
}

__global__ void k_fill(const int* __restrict__ src, const int* __restrict__ dst, int E) {
    int e = blockIdx.x * blockDim.x + threadIdx.x;
    if (e < E) {
        int d = dst[e];
        int pos = atomicAdd(&g_cursor[d], 1);
        EdgeRec r;
        r.src = src[e]; r.eid = e; r.ae1 = g_ae1a[e]; r.ae2 = g_ae2a[e];
        g_rec[g_rowptr[d] + pos] = r;
    }
}

// ------------------------- wE = We @ a_edge ---------------------------------
__global__ void k_we2(const float* __restrict__ We1, const float* __restrict__ ae1,
                      const float* __restrict__ We2, const float* __restrict__ ae2) {
    int warp = (blockIdx.x * blockDim.x + threadIdx.x) >> 5;
    int lane = threadIdx.x & 31;
    if (warp >= 2 * EDIM) return;
    int which = warp >= EDIM;
    int r = warp - which * EDIM;
    const float* We = which ? We2 : We1;
    const float* ae = which ? ae2 : ae1;
    float p = 0.f;
    for (int k = lane; k < HH; k += 32) p += We[r * HH + k] * ae[k];
    p = warpSum(p);
    if (lane == 0) { if (which) g_wE2[r] = p; else g_wE1[r] = p; }
}

// ------------------------- per-edge alpha_e (+deg) ---------------------------
__global__ void k_edge_ae(const float* __restrict__ ef, const int* __restrict__ dst, int E) {
    int gid = blockIdx.x * blockDim.x + threadIdx.x;
    int e = gid >> 3;
    int sub = gid & 7;
    if (e >= E) return;
    const float* row = ef + (size_t)e * EDIM;
    float p1 = 0.f, p2 = 0.f;
    for (int j = sub; j < EDIM; j += 8) {
        float v = row[j];
        p1 += v * g_wE1[j];
        p2 += v * g_wE2[j];
    }
#pragma unroll
    for (int o = 4; o; o >>= 1) {
        p1 += __shfl_xor_sync(0xffffffffu, p1, o);
        p2 += __shfl_xor_sync(0xffffffffu, p2, o);
    }
    if (sub == 0) {
        g_ae1a[e] = p1;
        g_ae2a[e] = p2;
        int d = dst[e];
        atomicAdd(&g_sumae1[d], p1);
        atomicAdd(&g_sumae2[d], p2);
        atomicAdd(&g_deg[d], 1);
    }
}

// ------------------------- bf16 hi/mid split ---------------------------------
__device__ __forceinline__ void split1(float x, __nv_bfloat16& h, __nv_bfloat16& m) {
    h = __float2bfloat16(x);
    m = __float2bfloat16(x - __bfloat162float(h));
}
__global__ void k_splitA(const float* __restrict__ Xext, int total4) {
    int i = blockIdx.x * blockDim.x + threadIdx.x;
    if (i >= total4) return;
    const float* X = Xext ? Xext : g_out;
    float4 v = ((const float4*)X)[i];
    __nv_bfloat16 h0, h1, h2, h3, m0, m1, m2, m3;
    split1(v.x, h0, m0); split1(v.y, h1, m1);
    split1(v.z, h2, m2); split1(v.w, h3, m3);
    ((__nv_bfloat162*)g_Ah)[2 * i]     = __nv_bfloat162(h0, h1);
    ((__nv_bfloat162*)g_Ah)[2 * i + 1] = __nv_bfloat162(h2, h3);
    ((__nv_bfloat162*)g_Am)[2 * i]     = __nv_bfloat162(m0, m1);
    ((__nv_bfloat162*)g_Am)[2 * i + 1] = __nv_bfloat162(m2, m3);
}
// W[K,128] -> Wt[128,K] bf16 hi/mid
__global__ void k_splitW(const float* __restrict__ W, int K) {
    int i = blockIdx.x * blockDim.x + threadIdx.x;
    if (i >= 128 * K) return;
    int nrow = i / K, k = i - nrow * K;
    __nv_bfloat16 h, m;
    split1(W[(size_t)k * 128 + nrow], h, m);
    g_Bh[i] = h;
    g_Bm[i] = m;
}

// ------------------------- bf16-split HMMA GEMM ------------------------------
// C[M,128] = A @ W ; D = Ah·Bh + Ah·Bm + Am·Bh, fp32 accum.
// 128x128 block, 8 warps (4 M x 2 N), warp tile 32x64, cp.async double buffer.
// OOB A rows: source row clamped to M-1 (tail smem rows hold duplicates; every
// consumer of those rows is gr<M guarded).
#define STRIDE 40                      // bf16 elems per smem row (32 + 8 pad = 80B)
#define MATB   (128 * STRIDE * 2)      // 10240 B per matrix per buffer
#define GEMM_SMEM (8 * MATB + 128 * 4 * 4)

__global__ __launch_bounds__(256)
void k_gemm(const float* __restrict__ avs, const float* __restrict__ avd, int M, int K) {
    extern __shared__ char smc[];
    float* sDot = (float*)(smc + 8 * MATB);   // [128][4] : ps0 ps1 pd0 pd1
    const int tid = threadIdx.x, lane = tid & 31, wid = tid >> 5;
    const int wm = wid & 3, wn = wid >> 2;
    const int blockRow = blockIdx.x * 128;
    const int tk = (lane & 3) * 2, gq = lane >> 2;

    const __nv_bfloat16* gmat[4] = {g_Ah, g_Am, g_Bh, g_Bm};

    float acc[2][8][4];
#pragma unroll
    for (int a = 0; a < 2; a++)
#pragma unroll
        for (int b = 0; b < 8; b++)
#pragma unroll
            for (int c = 0; c < 4; c++) acc[a][b][c] = 0.f;

    const int nc = K >> 5;
    // issue chunk `ch` into buffer `buf`
    auto issue = [&](int ch, int buf) {
#pragma unroll
        for (int m = 0; m < 4; m++) {
            const __nv_bfloat16* G = gmat[m];
            const bool isA = m < 2;
#pragma unroll
            for (int it = 0; it < 2; it++) {
                int idx = tid + it * 256;          // 0..511
                int row = idx >> 2, part = idx & 3;
                uint32_t dsm = smem_u32(smc + (buf * 4 + m) * MATB + row * 80 + part * 16);
                int grow = isA ? min(blockRow + row, M - 1) : row;
                const __nv_bfloat16* src = G + (size_t)grow * K + ch * 32 + part * 8;
                cp16(dsm, src);
            }
        }
    };

    issue(0, 0);
    CP_COMMIT();

    for (int c = 0; c < nc; c++) {
        CP_WAIT0();
        __syncthreads();
        if (c + 1 < nc) { issue(c + 1, (c + 1) & 1); CP_COMMIT(); }
        const int buf = c & 1;
        const __nv_bfloat16* Ah = (const __nv_bfloat16*)(smc + (buf * 4 + 0) * MATB);
        const __nv_bfloat16* Am = (const __nv_bfloat16*)(smc + (buf * 4 + 1) * MATB);
        const __nv_bfloat16* Bh = (const __nv_bfloat16*)(smc + (buf * 4 + 2) * MATB);
        const __nv_bfloat16* Bm = (const __nv_bfloat16*)(smc + (buf * 4 + 3) * MATB);
#pragma unroll
        for (int kk = 0; kk < 32; kk += 16) {
            uint32_t ah[2][4], am[2][4];
#pragma unroll
            for (int mi = 0; mi < 2; mi++) {
                int r0 = wm * 32 + mi * 16 + gq;
                ah[mi][0] = *(const uint32_t*)(Ah + r0 * STRIDE + kk + tk);
                ah[mi][1] = *(const uint32_t*)(Ah + (r0 + 8) * STRIDE + kk + tk);
                ah[mi][2] = *(const uint32_t*)(Ah + r0 * STRIDE + kk + 8 + tk);
                ah[mi][3] = *(const uint32_t*)(Ah + (r0 + 8) * STRIDE + kk + 8 + tk);
                am[mi][0] = *(const uint32_t*)(Am + r0 * STRIDE + kk + tk);
                am[mi][1] = *(const uint32_t*)(Am + (r0 + 8) * STRIDE + kk + tk);
                am[mi][2] = *(const uint32_t*)(Am + r0 * STRIDE + kk + 8 + tk);
                am[mi][3] = *(const uint32_t*)(Am + (r0 + 8) * STRIDE + kk + 8 + tk);
            }
            uint32_t bh[8][2], bm[8][2];
#pragma unroll
            for (int ni = 0; ni < 8; ni++) {
                int n0 = wn * 64 + ni * 8 + gq;
                bh[ni][0] = *(const uint32_t*)(Bh + n0 * STRIDE + kk + tk);
                bh[ni][1] = *(const uint32_t*)(Bh + n0 * STRIDE + kk + 8 + tk);
                bm[ni][0] = *(const uint32_t*)(Bm + n0 * STRIDE + kk + tk);
                bm[ni][1] = *(const uint32_t*)(Bm + n0 * STRIDE + kk + 8 + tk);
            }
#pragma unroll
            for (int mi = 0; mi < 2; mi++)
#pragma unroll
                for (int ni = 0; ni < 8; ni++) {
                    mma_bf16(acc[mi][ni], ah[mi], bh[ni]);
                    mma_bf16(acc[mi][ni], ah[mi], bm[ni]);
                    mma_bf16(acc[mi][ni], am[mi], bh[ni]);
                }
        }
    }
    __syncthreads();

    // epilogue: store C rows + fused a_src/a_dst dots
#pragma unroll
    for (int mi = 0; mi < 2; mi++) {
        int rloc = wm * 32 + mi * 16 + gq;
        int gr = blockRow + rloc;
        float psA = 0.f, pdA = 0.f, psB = 0.f, pdB = 0.f;
#pragma unroll
        for (int ni = 0; ni < 8; ni++) {
            int col = wn * 64 + ni * 8 + tk;
            float c0 = acc[mi][ni][0], c1 = acc[mi][ni][1];
            float c2 = acc[mi][ni][2], c3 = acc[mi][ni][3];
            if (gr < M) { float2 v = make_float2(c0, c1);
                          *(float2*)(g_h + (size_t)gr * 128 + col) = v; }
            if (gr + 8 < M) { float2 v = make_float2(c2, c3);
                              *(float2*)(g_h + (size_t)(gr + 8) * 128 + col) = v; }
            float s0 = avs[col], s1 = avs[col + 1];
            float d0 = avd[col], d1 = avd[col + 1];
            psA += c0 * s0 + c1 * s1; pdA += c0 * d0 + c1 * d1;
            psB += c2 * s0 + c3 * s1; pdB += c2 * d0 + c3 * d1;
        }
#pragma unroll
        for (int o = 1; o <= 2; o <<= 1) {
            psA += __shfl_xor_sync(0xffffffffu, psA, o);
            pdA += __shfl_xor_sync(0xffffffffu, pdA, o);
            psB += __shfl_xor_sync(0xffffffffu, psB, o);
            pdB += __shfl_xor_sync(0xffffffffu, pdB, o);
        }
        if ((lane & 3) == 0) {
            sDot[rloc * 4 + wn] = psA;       sDot[rloc * 4 + 2 + wn] = pdA;
            sDot[(rloc + 8) * 4 + wn] = psB; sDot[(rloc + 8) * 4 + 2 + wn] = pdB;
        }
    }
    __syncthreads();
    if (tid < 128) {
        int gr = blockRow + tid;
        if (gr < M) {
            g_as[gr] = sDot[tid * 4] + sDot[tid * 4 + 1];
            g_ad[gr] = sDot[tid * 4 + 2] + sDot[tid * 4 + 3];
        }
    }
}

// ------------------------- fused softmax + aggregate -------------------------
__global__ __launch_bounds__(256)
void k_aggregate(const float* __restrict__ bias, int n, int layer2) {
    int warp = (blockIdx.x * blockDim.x + threadIdx.x) >> 5;
    int lane = threadIdx.x & 31;
    if (warp >= n) return;
    int v = warp;
    int r0 = g_rowptr[v], r1 = g_rowptr[v + 1];
    int deg = r1 - r0;
    float adv = g_ad[v];
    float sA = layer2 ? g_sumae2[v] : g_sumae1[v];
    float aloop = lrelu(g_as[v] + adv + sA / (float)(deg > 0 ? deg : 1));

    float m = aloop;
    for (int i = r0 + lane; i < r1; i += 32) {
        EdgeRec r = g_rec[i];
        float ae = layer2 ? r.ae2 : r.ae1;
        m = fmaxf(m, lrelu(g_as[r.src] + adv + ae));
    }
    m = warpMax(m);

    float4 acc = make_float4(0.f, 0.f, 0.f, 0.f);
    float dsum = 0.f;
    for (int c0 = r0; c0 < r1; c0 += 32) {
        int i = c0 + lane;
        float w = 0.f;
        int s = 0;
        if (i < r1) {
            EdgeRec r = g_rec[i];
            s = r.src;
            float ae = layer2 ? r.ae2 : r.ae1;
            w = __expf(lrelu(g_as[s] + adv + ae) - m);
        }
        dsum += w;
        int cnt = min(32, r1 - c0);
        int j = 0;
        for (; j + 4 <= cnt; j += 4) {
            float w0 = __shfl_sync(0xffffffffu, w, j);
            float w1 = __shfl_sync(0xffffffffu, w, j + 1);
            float w2 = __shfl_sync(0xffffffffu, w, j + 2);
            float w3 = __shfl_sync(0xffffffffu, w, j + 3);
            int s0 = __shfl_sync(0xffffffffu, s, j);
            int s1 = __shfl_sync(0xffffffffu, s, j + 1);
            int s2 = __shfl_sync(0xffffffffu, s, j + 2);
            int s3 = __shfl_sync(0xffffffffu, s, j + 3);
            float4 h0 = ((const float4*)(g_h + (size_t)s0 * HH))[lane];
            float4 h1 = ((const float4*)(g_h + (size_t)s1 * HH))[lane];
            float4 h2 = ((const float4*)(g_h + (size_t)s2 * HH))[lane];
            float4 h3 = ((const float4*)(g_h + (size_t)s3 * HH))[lane];
            acc.x += w0 * h0.x + w1 * h1.x + w2 * h2.x + w3 * h3.x;
            acc.y += w0 * h0.y + w1 * h1.y + w2 * h2.y + w3 * h3.y;
            acc.z += w0 * h0.z + w1 * h1.z + w2 * h2.z + w3 * h3.z;
            acc.w += w0 * h0.w + w1 * h1.w + w2 * h2.w + w3 * h3.w;
        }
        for (; j < cnt; j++) {
            float wj = __shfl_sync(0xffffffffu, w, j);
            int sj = __shfl_sync(0xffffffffu, s, j);
            float4 hv = ((const float4*)(g_h + (size_t)sj * HH))[lane];
            acc.x += wj * hv.x; acc.y += wj * hv.y;
            acc.z += wj * hv.z; acc.w += wj * hv.w;
        }
    }
    float wl = __expf(aloop - m);
    {
        float4 hv = ((const float4*)(g_h + (size_t)v * HH))[lane];
        acc.x += wl * hv.x; acc.y += wl * hv.y;
        acc.z += wl * hv.z; acc.w += wl * hv.w;
    }
    float inv = 1.f / (warpSum(dsum) + wl);
    float4 b4 = ((const float4*)bias)[lane];
    float4 o;
    o.x = acc.x * inv + b4.x; o.y = acc.y * inv + b4.y;
    o.z = acc.z * inv + b4.z; o.w = acc.w * inv + b4.w;
    if (!layer2) {
        o.x = fmaxf(o.x, 0.f); o.y = fmaxf(o.y, 0.f);
        o.z = fmaxf(o.z, 0.f); o.w = fmaxf(o.w, 0.f);
    }
    ((float4*)(g_out + (size_t)v * HH))[lane] = o;
}

// ------------------------- decode -------------------------------------------
__global__ __launch_bounds__(256)
void k_decode_csr(int n) {
    int warp = (blockIdx.x * blockDim.x + threadIdx.x) >> 5;
    int lane = threadIdx.x & 31;
    if (warp >= n) return;
    int v = warp;
    int r0 = g_rowptr[v], r1 = g_rowptr[v + 1];
    float4 zd = ((const float4*)(g_out + (size_t)v * HH))[lane];
    int i = r0;
    for (; i + 2 <= r1; i += 2) {
        EdgeRec ra = g_rec[i], rb = g_rec[i + 1];
        float4 z0 = ((const float4*)(g_out + (size_t)ra.src * HH))[lane];
        float4 z1 = ((const float4*)(g_out + (size_t)rb.src * HH))[lane];
        float p0 = zd.x * z0.x + zd.y * z0.y + zd.z * z0.z + zd.w * z0.w;
        float p1 = zd.x * z1.x + zd.y * z1.y + zd.z * z1.z + zd.w * z1.w;
#pragma unroll
        for (int o = 16; o; o >>= 1) {
            p0 += __shfl_xor_sync(0xffffffffu, p0, o);
            p1 += __shfl_xor_sync(0xffffffffu, p1, o);
        }
        if (lane == 0) { g_res[ra.eid] = p0; g_res[rb.eid] = p1; }
    }
    if (i < r1) {
        EdgeRec ra = g_rec[i];
        float4 z0 = ((const float4*)(g_out + (size_t)ra.src * HH))[lane];
        float p0 = zd.x * z0.x + zd.y * z0.y + zd.z * z0.z + zd.w * z0.w;
        p0 = warpSum(p0);
        if (lane == 0) g_res[ra.eid] = p0;
    }
}

__global__ void k_fold(float* __restrict__ out, int half) {
    int i = blockIdx.x * blockDim.x + threadIdx.x;
    if (i < half) out[i] = g_res[i] + g_res[i + half];
}

// ------------------------- launch --------------------------------------------
extern "C" void kernel_launch(void* const* d_in, const int* in_sizes, int n_in,
                              void* d_out, int out_size) {
    const float* x   = (const float*)d_in[0];
    const int*   ei  = (const int*)d_in[1];
    const float* ef  = (const float*)d_in[2];
    const float* W1  = (const float*)d_in[4];
    const float* as1 = (const float*)d_in[5];
    const float* ad1 = (const float*)d_in[6];
    const float* We1 = (const float*)d_in[7];
    const float* ae1 = (const float*)d_in[8];
    const float* b1  = (const float*)d_in[9];
    const float* W2  = (const float*)d_in[10];
    const float* as2 = (const float*)d_in[11];
    const float* ad2 = (const float*)d_in[12];
    const float* We2 = (const float*)d_in[13];
    const float* ae2 = (const float*)d_in[14];
    const float* b2  = (const float*)d_in[15];

    const int E = in_sizes[1] / 2;
    const int N = in_sizes[0] / FIN;
    const int* src = ei;
    const int* dst = ei + E;

    cudaFuncSetAttribute(k_gemm, cudaFuncAttributeMaxDynamicSharedMemorySize, GEMM_SMEM);

    // CSR + edge preprocessing
    k_zero<<<(N + 255) / 256, 256>>>(N);
    k_we2<<<(2 * EDIM * 32 + 255) / 256, 256>>>(We1, ae1, We2, ae2);
    k_edge_ae<<<((size_t)E * 8 + 255) / 256, 256>>>(ef, dst, E);
    k_scan<<<1, 1024>>>(N);
    k_fill<<<(E + 255) / 256, 256>>>(src, dst, E);

    // layer 1
    k_splitW<<<(128 * FIN + 255) / 256, 256>>>(W1, FIN);
    k_splitA<<<((N * FIN / 4) + 255) / 256, 256>>>(x, N * FIN / 4);
    k_gemm<<<(N + 127) / 128, 256, GEMM_SMEM>>>(as1, ad1, N, FIN);
    k_aggregate<<<(N * 32 + 255) / 256, 256>>>(b1, N, 0);

    // layer 2
    k_splitW<<<(128 * HH + 255) / 256, 256>>>(W2, HH);
    k_splitA<<<((N * HH / 4) + 255) / 256, 256>>>(nullptr, N * HH / 4);
    k_gemm<<<(N + 127) / 128, 256, GEMM_SMEM>>>(as2, ad2, N, HH);
    k_aggregate<<<(N * 32 + 255) / 256, 256>>>(b2, N, 1);

    // decode
    k_decode_csr<<<(N * 32 + 255) / 256, 256>>>(N);
    int half = E / 2;
    k_fold<<<(half + 255) / 256, 256>>>((float*)d_out, half);
}

// round 12
// speedup vs baseline: 1.7386x; 1.1300x over previous
#include <cuda_runtime.h>
#include <cuda_bf16.h>
#include <cstdint>

#define NN   50000
#define EE   800000
#define HH   128
#define FIN  256
#define EDIM 60
#define NEG_SLOPE 0.2f

// ------------------------- scratch ------------------------------------------
struct __align__(16) EdgeRec { int src; int eid; float ae1; float ae2; };

__device__ float g_h[(size_t)NN * HH];
__device__ float g_out[(size_t)NN * HH];
__device__ float g_ae1a[EE];
__device__ float g_ae2a[EE];
__device__ EdgeRec g_rec[EE];
__device__ int   g_deg[NN];
__device__ int   g_cursor[NN];
__device__ int   g_rowptr[NN + 1];
__device__ int   g_bsum[64];
__device__ int   g_boff[64];
__device__ float g_as[NN];
__device__ float g_ad[NN];
__device__ float g_sumae1[NN];
__device__ float g_sumae2[NN];
__device__ float g_wE1[EDIM];
__device__ float g_wE2[EDIM];
// bf16 split operands (A row-major [M][K]; B as Wt[n][k], n=out col)
__device__ __nv_bfloat16 g_Ah[(size_t)NN * FIN];
__device__ __nv_bfloat16 g_Am[(size_t)NN * FIN];
__device__ __nv_bfloat16 g_Bh[128 * FIN];
__device__ __nv_bfloat16 g_Bm[128 * FIN];

// ------------------------- helpers ------------------------------------------
__device__ __forceinline__ float warpSum(float v) {
#pragma unroll
    for (int o = 16; o; o >>= 1) v += __shfl_xor_sync(0xffffffffu, v, o);
    return v;
}
__device__ __forceinline__ float warpMax(float v) {
#pragma unroll
    for (int o = 16; o; o >>= 1) v = fmaxf(v, __shfl_xor_sync(0xffffffffu, v, o));
    return v;
}
__device__ __forceinline__ float lrelu(float a) { return a > 0.f ? a : NEG_SLOPE * a; }

__device__ __forceinline__ uint32_t smem_u32(const void* p) {
    uint32_t a;
    asm("{ .reg .u64 t; cvta.to.shared.u64 t, %1; cvt.u32.u64 %0, t; }" : "=r"(a) : "l"(p));
    return a;
}
__device__ __forceinline__ void cp16(uint32_t dsm, const void* src) {
    asm volatile("cp.async.cg.shared.global [%0], [%1], 16;"
                 :: "r"(dsm), "l"(src) : "memory");
}
#define CP_COMMIT() asm volatile("cp.async.commit_group;" ::: "memory")
#define CP_WAIT0()  asm volatile("cp.async.wait_group 0;" ::: "memory")

// mma.sync m16n8k16 bf16 (baseline PTX, valid at compute_103)
__device__ __forceinline__ void mma_bf16(float* c, const uint32_t* a, const uint32_t* b) {
    asm volatile(
        "mma.sync.aligned.m16n8k16.row.col.f32.bf16.bf16.f32 "
        "{%0,%1,%2,%3}, {%4,%5,%6,%7}, {%8,%9}, {%0,%1,%2,%3};"
        : "+f"(c[0]), "+f"(c[1]), "+f"(c[2]), "+f"(c[3])
        : "r"(a[0]), "r"(a[1]), "r"(a[2]), "r"(a[3]), "r"(b[0]), "r"(b[1]));
}

// ------------------------- init ---------------------------------------------
__global__ void k_zero(int n) {
    int i = blockIdx.x * blockDim.x + threadIdx.x;
    if (i < n) { g_deg[i] = 0; g_cursor[i] = 0; g_sumae1[i] = 0.f; g_sumae2[i] = 0.f; }
}
__global__ void k_zero_out(float* __restrict__ out, int n) {
    int i = blockIdx.x * blockDim.x + threadIdx.x;
    if (i < n) out[i] = 0.f;
}

// ------------------------- parallel scan (3 kernels) -------------------------
// stage 1: per-block (1024 elems) inclusive scan -> g_rowptr[i+1] (local), block total
__global__ __launch_bounds__(1024)
void k_scan1(int n) {
    __shared__ int wsum[32];
    int i = blockIdx.x * 1024 + threadIdx.x;
    int lane = threadIdx.x & 31, w = threadIdx.x >> 5;
    int v = (i < n) ? g_deg[i] : 0;
    int p = v;
#pragma unroll
    for (int o = 1; o < 32; o <<= 1) {
        int t = __shfl_up_sync(0xffffffffu, p, o);
        if (lane >= o) p += t;
    }
    if (lane == 31) wsum[w] = p;
    __syncthreads();
    if (w == 0) {
        int s = wsum[lane];
#pragma unroll
        for (int o = 1; o < 32; o <<= 1) {
            int t = __shfl_up_sync(0xffffffffu, s, o);
            if (lane >= o) s += t;
        }
        wsum[lane] = s;
    }
    __syncthreads();
    int incl = p + (w > 0 ? wsum[w - 1] : 0);
    if (i < n) g_rowptr[i + 1] = incl;
    if (threadIdx.x == 1023) g_bsum[blockIdx.x] = incl;
}
// stage 2: scan block totals (nb <= 64), one 64-thread block
__global__ void k_scan2(int nb) {
    __shared__ int sm[64];
    int tid = threadIdx.x;
    int v = (tid < nb) ? g_bsum[tid] : 0;
    sm[tid] = v;
    __syncthreads();
#pragma unroll
    for (int off = 1; off < 64; off <<= 1) {
        int t = (tid >= off) ? sm[tid - off] : 0;
        __syncthreads();
        sm[tid] += t;
        __syncthreads();
    }
    g_boff[tid] = sm[tid] - v;   // exclusive
}
// stage 3: add block offsets
__global__ void k_scan3(int n) {
    int i = blockIdx.x * blockDim.x + threadIdx.x;
    if (i == 0) g_rowptr[0] = 0;
    if (i < n) g_rowptr[i + 1] += g_boff[i >> 10];
}

__global__ void k_fill(const int* __restrict__ src, const int* __restrict__ dst, int E) {
    int e = blockIdx.x * blockDim.x + threadIdx.x;
    if (e < E) {
        int d = dst[e];
        int pos = atomicAdd(&g_cursor[d], 1);
        EdgeRec r;
        r.src = src[e]; r.eid = e; r.ae1 = g_ae1a[e]; r.ae2 = g_ae2a[e];
        g_rec[g_rowptr[d] + pos] = r;
    }
}

// ------------------------- wE = We @ a_edge ---------------------------------
__global__ void k_we2(const float* __restrict__ We1, const float* __restrict__ ae1,
                      const float* __restrict__ We2, const float* __restrict__ ae2) {
    int warp = (blockIdx.x * blockDim.x + threadIdx.x) >> 5;
    int lane = threadIdx.x & 31;
    if (warp >= 2 * EDIM) return;
    int which = warp >= EDIM;
    int r = warp - which * EDIM;
    const float* We = which ? We2 : We1;
    const float* ae = which ? ae2 : ae1;
    float p = 0.f;
    for (int k = lane; k < HH; k += 32) p += We[r * HH + k] * ae[k];
    p = warpSum(p);
    if (lane == 0) { if (which) g_wE2[r] = p; else g_wE1[r] = p; }
}

// ------------------------- per-edge alpha_e (+deg) ---------------------------
__global__ void k_edge_ae(const float* __restrict__ ef, const int* __restrict__ dst, int E) {
    int gid = blockIdx.x * blockDim.x + threadIdx.x;
    int e = gid >> 3;
    int sub = gid & 7;
    if (e >= E) return;
    const float* row = ef + (size_t)e * EDIM;
    float p1 = 0.f, p2 = 0.f;
    for (int j = sub; j < EDIM; j += 8) {
        float v = row[j];
        p1 += v * g_wE1[j];
        p2 += v * g_wE2[j];
    }
#pragma unroll
    for (int o = 4; o; o >>= 1) {
        p1 += __shfl_xor_sync(0xffffffffu, p1, o);
        p2 += __shfl_xor_sync(0xffffffffu, p2, o);
    }
    if (sub == 0) {
        g_ae1a[e] = p1;
        g_ae2a[e] = p2;
        int d = dst[e];
        atomicAdd(&g_sumae1[d], p1);
        atomicAdd(&g_sumae2[d], p2);
        atomicAdd(&g_deg[d], 1);
    }
}

// ------------------------- bf16 hi/mid split ---------------------------------
__device__ __forceinline__ void split1(float x, __nv_bfloat16& h, __nv_bfloat16& m) {
    h = __float2bfloat16(x);
    m = __float2bfloat16(x - __bfloat162float(h));
}
__global__ void k_splitA(const float* __restrict__ Xext, int total4) {
    int i = blockIdx.x * blockDim.x + threadIdx.x;
    if (i >= total4) return;
    const float* X = Xext ? Xext : g_out;
    float4 v = ((const float4*)X)[i];
    __nv_bfloat16 h0, h1, h2, h3, m0, m1, m2, m3;
    split1(v.x, h0, m0); split1(v.y, h1, m1);
    split1(v.z, h2, m2); split1(v.w, h3, m3);
    ((__nv_bfloat162*)g_Ah)[2 * i]     = __nv_bfloat162(h0, h1);
    ((__nv_bfloat162*)g_Ah)[2 * i + 1] = __nv_bfloat162(h2, h3);
    ((__nv_bfloat162*)g_Am)[2 * i]     = __nv_bfloat162(m0, m1);
    ((__nv_bfloat162*)g_Am)[2 * i + 1] = __nv_bfloat162(m2, m3);
}
// W[K,128] -> Wt[128,K] bf16 hi/mid
__global__ void k_splitW(const float* __restrict__ W, int K) {
    int i = blockIdx.x * blockDim.x + threadIdx.x;
    if (i >= 128 * K) return;
    int nrow = i / K, k = i - nrow * K;
    __nv_bfloat16 h, m;
    split1(W[(size_t)k * 128 + nrow], h, m);
    g_Bh[i] = h;
    g_Bm[i] = m;
}

// ------------------------- bf16-split HMMA GEMM ------------------------------
// C[M,128] = A @ W ; D = Ah·Bh + Ah·Bm + Am·Bh, fp32 accum.
// 128x128 block, 8 warps (4 M x 2 N), warp tile 32x64, cp.async double buffer.
#define STRIDE 40                      // bf16 elems per smem row (32 + 8 pad = 80B)
#define MATB   (128 * STRIDE * 2)      // 10240 B per matrix per buffer
#define GEMM_SMEM (8 * MATB + 128 * 4 * 4)

__global__ __launch_bounds__(256)
void k_gemm(const float* __restrict__ avs, const float* __restrict__ avd, int M, int K) {
    extern __shared__ char smc[];
    float* sDot = (float*)(smc + 8 * MATB);   // [128][4] : ps0 ps1 pd0 pd1
    const int tid = threadIdx.x, lane = tid & 31, wid = tid >> 5;
    const int wm = wid & 3, wn = wid >> 2;
    const int blockRow = blockIdx.x * 128;
    const int tk = (lane & 3) * 2, gq = lane >> 2;

    const __nv_bfloat16* gmat[4] = {g_Ah, g_Am, g_Bh, g_Bm};

    float acc[2][8][4];
#pragma unroll
    for (int a = 0; a < 2; a++)
#pragma unroll
        for (int b = 0; b < 8; b++)
#pragma unroll
            for (int c = 0; c < 4; c++) acc[a][b][c] = 0.f;

    const int nc = K >> 5;
    auto issue = [&](int ch, int buf) {
#pragma unroll
        for (int m = 0; m < 4; m++) {
            const __nv_bfloat16* G = gmat[m];
            const bool isA = m < 2;
#pragma unroll
            for (int it = 0; it < 2; it++) {
                int idx = tid + it * 256;          // 0..511
                int row = idx >> 2, part = idx & 3;
                uint32_t dsm = smem_u32(smc + (buf * 4 + m) * MATB + row * 80 + part * 16);
                int grow = isA ? min(blockRow + row, M - 1) : row;
                const __nv_bfloat16* src = G + (size_t)grow * K + ch * 32 + part * 8;
                cp16(dsm, src);
            }
        }
    };

    issue(0, 0);
    CP_COMMIT();

    for (int c = 0; c < nc; c++) {
        CP_WAIT0();
        __syncthreads();
        if (c + 1 < nc) { issue(c + 1, (c + 1) & 1); CP_COMMIT(); }
        const int buf = c & 1;
        const __nv_bfloat16* Ah = (const __nv_bfloat16*)(smc + (buf * 4 + 0) * MATB);
        const __nv_bfloat16* Am = (const __nv_bfloat16*)(smc + (buf * 4 + 1) * MATB);
        const __nv_bfloat16* Bh = (const __nv_bfloat16*)(smc + (buf * 4 + 2) * MATB);
        const __nv_bfloat16* Bm = (const __nv_bfloat16*)(smc + (buf * 4 + 3) * MATB);
#pragma unroll
        for (int kk = 0; kk < 32; kk += 16) {
            uint32_t ah[2][4], am[2][4];
#pragma unroll
            for (int mi = 0; mi < 2; mi++) {
                int r0 = wm * 32 + mi * 16 + gq;
                ah[mi][0] = *(const uint32_t*)(Ah + r0 * STRIDE + kk + tk);
                ah[mi][1] = *(const uint32_t*)(Ah + (r0 + 8) * STRIDE + kk + tk);
                ah[mi][2] = *(const uint32_t*)(Ah + r0 * STRIDE + kk + 8 + tk);
                ah[mi][3] = *(const uint32_t*)(Ah + (r0 + 8) * STRIDE + kk + 8 + tk);
                am[mi][0] = *(const uint32_t*)(Am + r0 * STRIDE + kk + tk);
                am[mi][1] = *(const uint32_t*)(Am + (r0 + 8) * STRIDE + kk + tk);
                am[mi][2] = *(const uint32_t*)(Am + r0 * STRIDE + kk + 8 + tk);
                am[mi][3] = *(const uint32_t*)(Am + (r0 + 8) * STRIDE + kk + 8 + tk);
            }
            uint32_t bh[8][2], bm[8][2];
#pragma unroll
            for (int ni = 0; ni < 8; ni++) {
                int n0 = wn * 64 + ni * 8 + gq;
                bh[ni][0] = *(const uint32_t*)(Bh + n0 * STRIDE + kk + tk);
                bh[ni][1] = *(const uint32_t*)(Bh + n0 * STRIDE + kk + 8 + tk);
                bm[ni][0] = *(const uint32_t*)(Bm + n0 * STRIDE + kk + tk);
                bm[ni][1] = *(const uint32_t*)(Bm + n0 * STRIDE + kk + 8 + tk);
            }
#pragma unroll
            for (int mi = 0; mi < 2; mi++)
#pragma unroll
                for (int ni = 0; ni < 8; ni++) {
                    mma_bf16(acc[mi][ni], ah[mi], bh[ni]);
                    mma_bf16(acc[mi][ni], ah[mi], bm[ni]);
                    mma_bf16(acc[mi][ni], am[mi], bh[ni]);
                }
        }
    }
    __syncthreads();

    // epilogue: store C rows + fused a_src/a_dst dots
#pragma unroll
    for (int mi = 0; mi < 2; mi++) {
        int rloc = wm * 32 + mi * 16 + gq;
        int gr = blockRow + rloc;
        float psA = 0.f, pdA = 0.f, psB = 0.f, pdB = 0.f;
#pragma unroll
        for (int ni = 0; ni < 8; ni++) {
            int col = wn * 64 + ni * 8 + tk;
            float c0 = acc[mi][ni][0], c1 = acc[mi][ni][1];
            float c2 = acc[mi][ni][2], c3 = acc[mi][ni][3];
            if (gr < M) { float2 v = make_float2(c0, c1);
                          *(float2*)(g_h + (size_t)gr * 128 + col) = v; }
            if (gr + 8 < M) { float2 v = make_float2(c2, c3);
                              *(float2*)(g_h + (size_t)(gr + 8) * 128 + col) = v; }
            float s0 = avs[col], s1 = avs[col + 1];
            float d0 = avd[col], d1 = avd[col + 1];
            psA += c0 * s0 + c1 * s1; pdA += c0 * d0 + c1 * d1;
            psB += c2 * s0 + c3 * s1; pdB += c2 * d0 + c3 * d1;
        }
#pragma unroll
        for (int o = 1; o <= 2; o <<= 1) {
            psA += __shfl_xor_sync(0xffffffffu, psA, o);
            pdA += __shfl_xor_sync(0xffffffffu, pdA, o);
            psB += __shfl_xor_sync(0xffffffffu, psB, o);
            pdB += __shfl_xor_sync(0xffffffffu, pdB, o);
        }
        if ((lane & 3) == 0) {
            sDot[rloc * 4 + wn] = psA;       sDot[rloc * 4 + 2 + wn] = pdA;
            sDot[(rloc + 8) * 4 + wn] = psB; sDot[(rloc + 8) * 4 + 2 + wn] = pdB;
        }
    }
    __syncthreads();
    if (tid < 128) {
        int gr = blockRow + tid;
        if (gr < M) {
            g_as[gr] = sDot[tid * 4] + sDot[tid * 4 + 1];
            g_ad[gr] = sDot[tid * 4 + 2] + sDot[tid * 4 + 3];
        }
    }
}

// ------------------------- fused softmax + aggregate -------------------------
__global__ __launch_bounds__(256)
void k_aggregate(const float* __restrict__ bias, int n, int layer2) {
    int warp = (blockIdx.x * blockDim.x + threadIdx.x) >> 5;
    int lane = threadIdx.x & 31;
    if (warp >= n) return;
    int v = warp;
    int r0 = g_rowptr[v], r1 = g_rowptr[v + 1];
    int deg = r1 - r0;
    float adv = g_ad[v];
    float sA = layer2 ? g_sumae2[v] : g_sumae1[v];
    float aloop = lrelu(g_as[v] + adv + sA / (float)(deg > 0 ? deg : 1));

    float m = aloop;
    for (int i = r0 + lane; i < r1; i += 32) {
        EdgeRec r = g_rec[i];
        float ae = layer2 ? r.ae2 : r.ae1;
        m = fmaxf(m, lrelu(g_as[r.src] + adv + ae));
    }
    m = warpMax(m);

    float4 acc = make_float4(0.f, 0.f, 0.f, 0.f);
    float dsum = 0.f;
    for (int c0 = r0; c0 < r1; c0 += 32) {
        int i = c0 + lane;
        float w = 0.f;
        int s = 0;
        if (i < r1) {
            EdgeRec r = g_rec[i];
            s = r.src;
            float ae = layer2 ? r.ae2 : r.ae1;
            w = __expf(lrelu(g_as[s] + adv + ae) - m);
        }
        dsum += w;
        int cnt = min(32, r1 - c0);
        int j = 0;
        for (; j + 4 <= cnt; j += 4) {
            float w0 = __shfl_sync(0xffffffffu, w, j);
            float w1 = __shfl_sync(0xffffffffu, w, j + 1);
            float w2 = __shfl_sync(0xffffffffu, w, j + 2);
            float w3 = __shfl_sync(0xffffffffu, w, j + 3);
            int s0 = __shfl_sync(0xffffffffu, s, j);
            int s1 = __shfl_sync(0xffffffffu, s, j + 1);
            int s2 = __shfl_sync(0xffffffffu, s, j + 2);
            int s3 = __shfl_sync(0xffffffffu, s, j + 3);
            float4 h0 = ((const float4*)(g_h + (size_t)s0 * HH))[lane];
            float4 h1 = ((const float4*)(g_h + (size_t)s1 * HH))[lane];
            float4 h2 = ((const float4*)(g_h + (size_t)s2 * HH))[lane];
            float4 h3 = ((const float4*)(g_h + (size_t)s3 * HH))[lane];
            acc.x += w0 * h0.x + w1 * h1.x + w2 * h2.x + w3 * h3.x;
            acc.y += w0 * h0.y + w1 * h1.y + w2 * h2.y + w3 * h3.y;
            acc.z += w0 * h0.z + w1 * h1.z + w2 * h2.z + w3 * h3.z;
            acc.w += w0 * h0.w + w1 * h1.w + w2 * h2.w + w3 * h3.w;
        }
        for (; j < cnt; j++) {
            float wj = __shfl_sync(0xffffffffu, w, j);
            int sj = __shfl_sync(0xffffffffu, s, j);
            float4 hv = ((const float4*)(g_h + (size_t)sj * HH))[lane];
            acc.x += wj * hv.x; acc.y += wj * hv.y;
            acc.z += wj * hv.z; acc.w += wj * hv.w;
        }
    }
    float wl = __expf(aloop - m);
    {
        float4 hv = ((const float4*)(g_h + (size_t)v * HH))[lane];
        acc.x += wl * hv.x; acc.y += wl * hv.y;
        acc.z += wl * hv.z; acc.w += wl * hv.w;
    }
    float inv = 1.f / (warpSum(dsum) + wl);
    float4 b4 = ((const float4*)bias)[lane];
    float4 o;
    o.x = acc.x * inv + b4.x; o.y = acc.y * inv + b4.y;
    o.z = acc.z * inv + b4.z; o.w = acc.w * inv + b4.w;
    if (!layer2) {
        o.x = fmaxf(o.x, 0.f); o.y = fmaxf(o.y, 0.f);
        o.z = fmaxf(o.z, 0.f); o.w = fmaxf(o.w, 0.f);
    }
    ((float4*)(g_out + (size_t)v * HH))[lane] = o;
}

// ------------------------- decode (direct atomic fold into out) --------------
__global__ __launch_bounds__(256)
void k_decode_csr(float* __restrict__ out, int half, int n) {
    int warp = (blockIdx.x * blockDim.x + threadIdx.x) >> 5;
    int lane = threadIdx.x & 31;
    if (warp >= n) return;
    int v = warp;
    int r0 = g_rowptr[v], r1 = g_rowptr[v + 1];
    float4 zd = ((const float4*)(g_out + (size_t)v * HH))[lane];
    int i = r0;
    for (; i + 2 <= r1; i += 2) {
        EdgeRec ra = g_rec[i], rb = g_rec[i + 1];
        float4 z0 = ((const float4*)(g_out + (size_t)ra.src * HH))[lane];
        float4 z1 = ((const float4*)(g_out + (size_t)rb.src * HH))[lane];
        float p0 = zd.x * z0.x + zd.y * z0.y + zd.z * z0.z + zd.w * z0.w;
        float p1 = zd.x * z1.x + zd.y * z1.y + zd.z * z1.z + zd.w * z1.w;
#pragma unroll
        for (int o = 16; o; o >>= 1) {
            p0 += __shfl_xor_sync(0xffffffffu, p0, o);
            p1 += __shfl_xor_sync(0xffffffffu, p1, o);
        }
        if (lane == 0) {
            int o0 = ra.eid >= half ? ra.eid - half : ra.eid;
            int o1 = rb.eid >= half ? rb.eid - half : rb.eid;
            atomicAdd(&out[o0], p0);
            atomicAdd(&out[o1], p1);
        }
    }
    if (i < r1) {
        EdgeRec ra = g_rec[i];
        float4 z0 = ((const float4*)(g_out + (size_t)ra.src * HH))[lane];
        float p0 = zd.x * z0.x + zd.y * z0.y + zd.z * z0.z + zd.w * z0.w;
        p0 = warpSum(p0);
        if (lane == 0) {
            int o0 = ra.eid >= half ? ra.eid - half : ra.eid;
            atomicAdd(&out[o0], p0);
        }
    }
}

// ------------------------- launch --------------------------------------------
extern "C" void kernel_launch(void* const* d_in, const int* in_sizes, int n_in,
                              void* d_out, int out_size) {
    const float* x   = (const float*)d_in[0];
    const int*   ei  = (const int*)d_in[1];
    const float* ef  = (const float*)d_in[2];
    const float* W1  = (const float*)d_in[4];
    const float* as1 = (const float*)d_in[5];
    const float* ad1 = (const float*)d_in[6];
    const float* We1 = (const float*)d_in[7];
    const float* ae1 = (const float*)d_in[8];
    const float* b1  = (const float*)d_in[9];
    const float* W2  = (const float*)d_in[10];
    const float* as2 = (const float*)d_in[11];
    const float* ad2 = (const float*)d_in[12];
    const float* We2 = (const float*)d_in[13];
    const float* ae2 = (const float*)d_in[14];
    const float* b2  = (const float*)d_in[15];

    const int E = in_sizes[1] / 2;
    const int N = in_sizes[0] / FIN;
    const int* src = ei;
    const int* dst = ei + E;
    const int half = E / 2;

    cudaFuncSetAttribute(k_gemm, cudaFuncAttributeMaxDynamicSharedMemorySize, GEMM_SMEM);

    // CSR + edge preprocessing
    k_zero<<<(N + 255) / 256, 256>>>(N);
    k_zero_out<<<(half + 255) / 256, 256>>>((float*)d_out, half);
    k_we2<<<(2 * EDIM * 32 + 255) / 256, 256>>>(We1, ae1, We2, ae2);
    k_edge_ae<<<((size_t)E * 8 + 255) / 256, 256>>>(ef, dst, E);
    k_scan1<<<(N + 1023) / 1024, 1024>>>(N);
    k_scan2<<<1, 64>>>((N + 1023) / 1024);
    k_scan3<<<(N + 255) / 256, 256>>>(N);
    k_fill<<<(E + 255) / 256, 256>>>(src, dst, E);

    // layer 1
    k_splitW<<<(128 * FIN + 255) / 256, 256>>>(W1, FIN);
    k_splitA<<<((N * FIN / 4) + 255) / 256, 256>>>(x, N * FIN / 4);
    k_gemm<<<(N + 127) / 128, 256, GEMM_SMEM>>>(as1, ad1, N, FIN);
    k_aggregate<<<(N * 32 + 255) / 256, 256>>>(b1, N, 0);

    // layer 2
    k_splitW<<<(128 * HH + 255) / 256, 256>>>(W2, HH);
    k_splitA<<<((N * HH / 4) + 255) / 256, 256>>>(nullptr, N * HH / 4);
    k_gemm<<<(N + 127) / 128, 256, GEMM_SMEM>>>(as2, ad2, N, HH);
    k_aggregate<<<(N * 32 + 255) / 256, 256>>>(b2, N, 1);

    // decode
    k_decode_csr<<<(N * 32 + 255) / 256, 256>>>((float*)d_out, half, N);
}

// round 14
// speedup vs baseline: 1.7857x; 1.0271x over previous
#include <cuda_runtime.h>
#include <cuda_bf16.h>
#include <cstdint>

#define NN   50000
#define EE   800000
#define HH   128
#define FIN  256
#define EDIM 60
#define NEG_SLOPE 0.2f

// ------------------------- scratch ------------------------------------------
struct __align__(16) EdgeRec { int src; int eid; float ae1; float ae2; };

__device__ float g_h[(size_t)NN * HH];
__device__ float g_out[(size_t)NN * HH];
__device__ float g_ae1a[EE];
__device__ float g_ae2a[EE];
__device__ EdgeRec g_rec[EE];
__device__ int   g_deg[NN];
__device__ int   g_cursor[NN];
__device__ int   g_rowptr[NN + 1];
__device__ int   g_bsum[64];
__device__ int   g_boff[64];
__device__ float g_as[NN];
__device__ float g_ad[NN];
__device__ float g_sumae1[NN];
__device__ float g_sumae2[NN];
__device__ float g_wE1[64];   // padded to 16 float4s
__device__ float g_wE2[64];
// bf16 split operands (A row-major [M][K]; B as Wt[n][k], n=out col)
__device__ __nv_bfloat16 g_Ah[(size_t)NN * FIN];
__device__ __nv_bfloat16 g_Am[(size_t)NN * FIN];
__device__ __nv_bfloat16 g_Bh[128 * FIN];
__device__ __nv_bfloat16 g_Bm[128 * FIN];

// ------------------------- helpers ------------------------------------------
__device__ __forceinline__ float warpSum(float v) {
#pragma unroll
    for (int o = 16; o; o >>= 1) v += __shfl_xor_sync(0xffffffffu, v, o);
    return v;
}
__device__ __forceinline__ float warpMax(float v) {
#pragma unroll
    for (int o = 16; o; o >>= 1) v = fmaxf(v, __shfl_xor_sync(0xffffffffu, v, o));
    return v;
}
__device__ __forceinline__ float lrelu(float a) { return a > 0.f ? a : NEG_SLOPE * a; }

__device__ __forceinline__ uint32_t smem_u32(const void* p) {
    uint32_t a;
    asm("{ .reg .u64 t; cvta.to.shared.u64 t, %1; cvt.u32.u64 %0, t; }" : "=r"(a) : "l"(p));
    return a;
}
__device__ __forceinline__ void cp16(uint32_t dsm, const void* src) {
    asm volatile("cp.async.cg.shared.global [%0], [%1], 16;"
                 :: "r"(dsm), "l"(src) : "memory");
}
#define CP_COMMIT() asm volatile("cp.async.commit_group;" ::: "memory")
#define CP_WAIT0()  asm volatile("cp.async.wait_group 0;" ::: "memory")

// mma.sync m16n8k16 bf16 (baseline PTX, valid at compute_103)
__device__ __forceinline__ void mma_bf16(float* c, const uint32_t* a, const uint32_t* b) {
    asm volatile(
        "mma.sync.aligned.m16n8k16.row.col.f32.bf16.bf16.f32 "
        "{%0,%1,%2,%3}, {%4,%5,%6,%7}, {%8,%9}, {%0,%1,%2,%3};"
        : "+f"(c[0]), "+f"(c[1]), "+f"(c[2]), "+f"(c[3])
        : "r"(a[0]), "r"(a[1]), "r"(a[2]), "r"(a[3]), "r"(b[0]), "r"(b[1]));
}

// ------------------------- init ---------------------------------------------
__global__ void k_zero(int n) {
    int i = blockIdx.x * blockDim.x + threadIdx.x;
    if (i < n) { g_deg[i] = 0; g_cursor[i] = 0; g_sumae1[i] = 0.f; g_sumae2[i] = 0.f; }
}
__global__ void k_zero_out(float* __restrict__ out, int n) {
    int i = blockIdx.x * blockDim.x + threadIdx.x;
    if (i < n) out[i] = 0.f;
}

// ------------------------- parallel scan (3 kernels) -------------------------
__global__ __launch_bounds__(1024)
void k_scan1(int n) {
    __shared__ int wsum[32];
    int i = blockIdx.x * 1024 + threadIdx.x;
    int lane = threadIdx.x & 31, w = threadIdx.x >> 5;
    int v = (i < n) ? g_deg[i] : 0;
    int p = v;
#pragma unroll
    for (int o = 1; o < 32; o <<= 1) {
        int t = __shfl_up_sync(0xffffffffu, p, o);
        if (lane >= o) p += t;
    }
    if (lane == 31) wsum[w] = p;
    __syncthreads();
    if (w == 0) {
        int s = wsum[lane];
#pragma unroll
        for (int o = 1; o < 32; o <<= 1) {
            int t = __shfl_up_sync(0xffffffffu, s, o);
            if (lane >= o) s += t;
        }
        wsum[lane] = s;
    }
    __syncthreads();
    int incl = p + (w > 0 ? wsum[w - 1] : 0);
    if (i < n) g_rowptr[i + 1] = incl;
    if (threadIdx.x == 1023) g_bsum[blockIdx.x] = incl;
}
__global__ void k_scan2(int nb) {
    __shared__ int sm[64];
    int tid = threadIdx.x;
    int v = (tid < nb) ? g_bsum[tid] : 0;
    sm[tid] = v;
    __syncthreads();
#pragma unroll
    for (int off = 1; off < 64; off <<= 1) {
        int t = (tid >= off) ? sm[tid - off] : 0;
        __syncthreads();
        sm[tid] += t;
        __syncthreads();
    }
    g_boff[tid] = sm[tid] - v;   // exclusive
}
__global__ void k_scan3(int n) {
    int i = blockIdx.x * blockDim.x + threadIdx.x;
    if (i == 0) g_rowptr[0] = 0;
    if (i < n) g_rowptr[i + 1] += g_boff[i >> 10];
}

__global__ void k_fill(const int* __restrict__ src, const int* __restrict__ dst, int E) {
    int e = blockIdx.x * blockDim.x + threadIdx.x;
    if (e < E) {
        int d = dst[e];
        int pos = atomicAdd(&g_cursor[d], 1);
        EdgeRec r;
        r.src = src[e]; r.eid = e; r.ae1 = g_ae1a[e]; r.ae2 = g_ae2a[e];
        g_rec[g_rowptr[d] + pos] = r;
    }
}

// ------------------------- wE = We @ a_edge (zero-padded to 64) --------------
__global__ void k_we2(const float* __restrict__ We1, const float* __restrict__ ae1,
                      const float* __restrict__ We2, const float* __restrict__ ae2) {
    int warp = (blockIdx.x * blockDim.x + threadIdx.x) >> 5;
    int lane = threadIdx.x & 31;
    if (warp >= 128) return;
    int which = warp >= 64;
    int r = warp - which * 64;
    float p = 0.f;
    if (r < EDIM) {
        const float* We = which ? We2 : We1;
        const float* ae = which ? ae2 : ae1;
        for (int k = lane; k < HH; k += 32) p += We[r * HH + k] * ae[k];
        p = warpSum(p);
    }
    if (lane == 0) { if (which) g_wE2[r] = p; else g_wE1[r] = p; }
}

// ------------------------- per-edge alpha_e (+deg), float4 -------------------
// half-warp (16 lanes) per edge; lane hl loads float4 #hl of the 240B row.
__global__ __launch_bounds__(256)
void k_edge_ae(const float* __restrict__ ef, const int* __restrict__ dst, int E) {
    int gwarp = (blockIdx.x * blockDim.x + threadIdx.x) >> 5;
    int lane = threadIdx.x & 31;
    int hf = lane >> 4;          // which edge of the pair
    int hl = lane & 15;          // lane within half-warp
    int e = gwarp * 2 + hf;
    bool ok = e < E;
    float p1 = 0.f, p2 = 0.f;
    if (ok && hl < 15) {
        float4 v = *(const float4*)(ef + (size_t)e * EDIM + hl * 4);
        float4 w1 = ((const float4*)g_wE1)[hl];
        float4 w2 = ((const float4*)g_wE2)[hl];
        p1 = v.x * w1.x + v.y * w1.y + v.z * w1.z + v.w * w1.w;
        p2 = v.x * w2.x + v.y * w2.y + v.z * w2.z + v.w * w2.w;
    }
#pragma unroll
    for (int o = 8; o; o >>= 1) {
        p1 += __shfl_xor_sync(0xffffffffu, p1, o);
        p2 += __shfl_xor_sync(0xffffffffu, p2, o);
    }
    if (ok && hl == 0) {
        g_ae1a[e] = p1;
        g_ae2a[e] = p2;
        int d = dst[e];
        atomicAdd(&g_sumae1[d], p1);
        atomicAdd(&g_sumae2[d], p2);
        atomicAdd(&g_deg[d], 1);
    }
}

// ------------------------- bf16 hi/mid split ---------------------------------
__device__ __forceinline__ void split1(float x, __nv_bfloat16& h, __nv_bfloat16& m) {
    h = __float2bfloat16(x);
    m = __float2bfloat16(x - __bfloat162float(h));
}
// layer-1 input x only (layer-2 split is fused into k_aggregate)
__global__ void k_splitA(const float* __restrict__ X, int total4) {
    int i = blockIdx.x * blockDim.x + threadIdx.x;
    if (i >= total4) return;
    float4 v = ((const float4*)X)[i];
    __nv_bfloat16 h0, h1, h2, h3, m0, m1, m2, m3;
    split1(v.x, h0, m0); split1(v.y, h1, m1);
    split1(v.z, h2, m2); split1(v.w, h3, m3);
    ((__nv_bfloat162*)g_Ah)[2 * i]     = __nv_bfloat162(h0, h1);
    ((__nv_bfloat162*)g_Ah)[2 * i + 1] = __nv_bfloat162(h2, h3);
    ((__nv_bfloat162*)g_Am)[2 * i]     = __nv_bfloat162(m0, m1);
    ((__nv_bfloat162*)g_Am)[2 * i + 1] = __nv_bfloat162(m2, m3);
}
// W[K,128] -> Wt[128,K] bf16 hi/mid
__global__ void k_splitW(const float* __restrict__ W, int K) {
    int i = blockIdx.x * blockDim.x + threadIdx.x;
    if (i >= 128 * K) return;
    int nrow = i / K, k = i - nrow * K;
    __nv_bfloat16 h, m;
    split1(W[(size_t)k * 128 + nrow], h, m);
    g_Bh[i] = h;
    g_Bm[i] = m;
}

// ------------------------- bf16-split HMMA GEMM ------------------------------
#define STRIDE 40                      // bf16 elems per smem row (32 + 8 pad = 80B)
#define MATB   (128 * STRIDE * 2)      // 10240 B per matrix per buffer
#define GEMM_SMEM (8 * MATB + 128 * 4 * 4)

__global__ __launch_bounds__(256)
void k_gemm(const float* __restrict__ avs, const float* __restrict__ avd, int M, int K) {
    extern __shared__ char smc[];
    float* sDot = (float*)(smc + 8 * MATB);   // [128][4]
    const int tid = threadIdx.x, lane = tid & 31, wid = tid >> 5;
    const int wm = wid & 3, wn = wid >> 2;
    const int blockRow = blockIdx.x * 128;
    const int tk = (lane & 3) * 2, gq = lane >> 2;

    const __nv_bfloat16* gmat[4] = {g_Ah, g_Am, g_Bh, g_Bm};

    float acc[2][8][4];
#pragma unroll
    for (int a = 0; a < 2; a++)
#pragma unroll
        for (int b = 0; b < 8; b++)
#pragma unroll
            for (int c = 0; c < 4; c++) acc[a][b][c] = 0.f;

    const int nc = K >> 5;
    auto issue = [&](int ch, int buf) {
#pragma unroll
        for (int m = 0; m < 4; m++) {
            const __nv_bfloat16* G = gmat[m];
            const bool isA = m < 2;
#pragma unroll
            for (int it = 0; it < 2; it++) {
                int idx = tid + it * 256;
                int row = idx >> 2, part = idx & 3;
                uint32_t dsm = smem_u32(smc + (buf * 4 + m) * MATB + row * 80 + part * 16);
                int grow = isA ? min(blockRow + row, M - 1) : row;
                const __nv_bfloat16* src = G + (size_t)grow * K + ch * 32 + part * 8;
                cp16(dsm, src);
            }
        }
    };

    issue(0, 0);
    CP_COMMIT();

    for (int c = 0; c < nc; c++) {
        CP_WAIT0();
        __syncthreads();
        if (c + 1 < nc) { issue(c + 1, (c + 1) & 1); CP_COMMIT(); }
        const int buf = c & 1;
        const __nv_bfloat16* Ah = (const __nv_bfloat16*)(smc + (buf * 4 + 0) * MATB);
        const __nv_bfloat16* Am = (const __nv_bfloat16*)(smc + (buf * 4 + 1) * MATB);
        const __nv_bfloat16* Bh = (const __nv_bfloat16*)(smc + (buf * 4 + 2) * MATB);
        const __nv_bfloat16* Bm = (const __nv_bfloat16*)(smc + (buf * 4 + 3) * MATB);
#pragma unroll
        for (int kk = 0; kk < 32; kk += 16) {
            uint32_t ah[2][4], am[2][4];
#pragma unroll
            for (int mi = 0; mi < 2; mi++) {
                int r0 = wm * 32 + mi * 16 + gq;
                ah[mi][0] = *(const uint32_t*)(Ah + r0 * STRIDE + kk + tk);
                ah[mi][1] = *(const uint32_t*)(Ah + (r0 + 8) * STRIDE + kk + tk);
                ah[mi][2] = *(const uint32_t*)(Ah + r0 * STRIDE + kk + 8 + tk);
                ah[mi][3] = *(const uint32_t*)(Ah + (r0 + 8) * STRIDE + kk + 8 + tk);
                am[mi][0] = *(const uint32_t*)(Am + r0 * STRIDE + kk + tk);
                am[mi][1] = *(const uint32_t*)(Am + (r0 + 8) * STRIDE + kk + tk);
                am[mi][2] = *(const uint32_t*)(Am + r0 * STRIDE + kk + 8 + tk);
                am[mi][3] = *(const uint32_t*)(Am + (r0 + 8) * STRIDE + kk + 8 + tk);
            }
            uint32_t bh[8][2], bm[8][2];
#pragma unroll
            for (int ni = 0; ni < 8; ni++) {
                int n0 = wn * 64 + ni * 8 + gq;
                bh[ni][0] = *(const uint32_t*)(Bh + n0 * STRIDE + kk + tk);
                bh[ni][1] = *(const uint32_t*)(Bh + n0 * STRIDE + kk + 8 + tk);
                bm[ni][0] = *(const uint32_t*)(Bm + n0 * STRIDE + kk + tk);
                bm[ni][1] = *(const uint32_t*)(Bm + n0 * STRIDE + kk + 8 + tk);
            }
#pragma unroll
            for (int mi = 0; mi < 2; mi++)
#pragma unroll
                for (int ni = 0; ni < 8; ni++) {
                    mma_bf16(acc[mi][ni], ah[mi], bh[ni]);
                    mma_bf16(acc[mi][ni], ah[mi], bm[ni]);
                    mma_bf16(acc[mi][ni], am[mi], bh[ni]);
                }
        }
    }
    __syncthreads();

    // epilogue: store C rows + fused a_src/a_dst dots
#pragma unroll
    for (int mi = 0; mi < 2; mi++) {
        int rloc = wm * 32 + mi * 16 + gq;
        int gr = blockRow + rloc;
        float psA = 0.f, pdA = 0.f, psB = 0.f, pdB = 0.f;
#pragma unroll
        for (int ni = 0; ni < 8; ni++) {
            int col = wn * 64 + ni * 8 + tk;
            float c0 = acc[mi][ni][0], c1 = acc[mi][ni][1];
            float c2 = acc[mi][ni][2], c3 = acc[mi][ni][3];
            if (gr < M) { float2 v = make_float2(c0, c1);
                          *(float2*)(g_h + (size_t)gr * 128 + col) = v; }
            if (gr + 8 < M) { float2 v = make_float2(c2, c3);
                              *(float2*)(g_h + (size_t)(gr + 8) * 128 + col) = v; }
            float s0 = avs[col], s1 = avs[col + 1];
            float d0 = avd[col], d1 = avd[col + 1];
            psA += c0 * s0 + c1 * s1; pdA += c0 * d0 + c1 * d1;
            psB += c2 * s0 + c3 * s1; pdB += c2 * d0 + c3 * d1;
        }
#pragma unroll
        for (int o = 1; o <= 2; o <<= 1) {
            psA += __shfl_xor_sync(0xffffffffu, psA, o);
            pdA += __shfl_xor_sync(0xffffffffu, pdA, o);
            psB += __shfl_xor_sync(0xffffffffu, psB, o);
            pdB += __shfl_xor_sync(0xffffffffu, pdB, o);
        }
        if ((lane & 3) == 0) {
            sDot[rloc * 4 + wn] = psA;       sDot[rloc * 4 + 2 + wn] = pdA;
            sDot[(rloc + 8) * 4 + wn] = psB; sDot[(rloc + 8) * 4 + 2 + wn] = pdB;
        }
    }
    __syncthreads();
    if (tid < 128) {
        int gr = blockRow + tid;
        if (gr < M) {
            g_as[gr] = sDot[tid * 4] + sDot[tid * 4 + 1];
            g_ad[gr] = sDot[tid * 4 + 2] + sDot[tid * 4 + 3];
        }
    }
}

// ------------------------- fused softmax + aggregate -------------------------
// layer 1 additionally writes the bf16 split of its output into g_Ah/g_Am
// (feeds the layer-2 GEMM, eliminating the second splitA pass).
__global__ __launch_bounds__(256)
void k_aggregate(const float* __restrict__ bias, int n, int layer2) {
    int warp = (blockIdx.x * blockDim.x + threadIdx.x) >> 5;
    int lane = threadIdx.x & 31;
    if (warp >= n) return;
    int v = warp;
    int r0 = g_rowptr[v], r1 = g_rowptr[v + 1];
    int deg = r1 - r0;
    float adv = g_ad[v];
    float sA = layer2 ? g_sumae2[v] : g_sumae1[v];
    float aloop = lrelu(g_as[v] + adv + sA / (float)(deg > 0 ? deg : 1));

    float m = aloop;
    for (int i = r0 + lane; i < r1; i += 32) {
        EdgeRec r = g_rec[i];
        float ae = layer2 ? r.ae2 : r.ae1;
        m = fmaxf(m, lrelu(g_as[r.src] + adv + ae));
    }
    m = warpMax(m);

    float4 acc = make_float4(0.f, 0.f, 0.f, 0.f);
    float dsum = 0.f;
    for (int c0 = r0; c0 < r1; c0 += 32) {
        int i = c0 + lane;
        float w = 0.f;
        int s = 0;
        if (i < r1) {
            EdgeRec r = g_rec[i];
            s = r.src;
            float ae = layer2 ? r.ae2 : r.ae1;
            w = __expf(lrelu(g_as[s] + adv + ae) - m);
        }
        dsum += w;
        int cnt = min(32, r1 - c0);
        int j = 0;
        for (; j + 4 <= cnt; j += 4) {
            float w0 = __shfl_sync(0xffffffffu, w, j);
            float w1 = __shfl_sync(0xffffffffu, w, j + 1);
            float w2 = __shfl_sync(0xffffffffu, w, j + 2);
            float w3 = __shfl_sync(0xffffffffu, w, j + 3);
            int s0 = __shfl_sync(0xffffffffu, s, j);
            int s1 = __shfl_sync(0xffffffffu, s, j + 1);
            int s2 = __shfl_sync(0xffffffffu, s, j + 2);
            int s3 = __shfl_sync(0xffffffffu, s, j + 3);
            float4 h0 = ((const float4*)(g_h + (size_t)s0 * HH))[lane];
            float4 h1 = ((const float4*)(g_h + (size_t)s1 * HH))[lane];
            float4 h2 = ((const float4*)(g_h + (size_t)s2 * HH))[lane];
            float4 h3 = ((const float4*)(g_h + (size_t)s3 * HH))[lane];
            acc.x += w0 * h0.x + w1 * h1.x + w2 * h2.x + w3 * h3.x;
            acc.y += w0 * h0.y + w1 * h1.y + w2 * h2.y + w3 * h3.y;
            acc.z += w0 * h0.z + w1 * h1.z + w2 * h2.z + w3 * h3.z;
            acc.w += w0 * h0.w + w1 * h1.w + w2 * h2.w + w3 * h3.w;
        }
        for (; j < cnt; j++) {
            float wj = __shfl_sync(0xffffffffu, w, j);
            int sj = __shfl_sync(0xffffffffu, s, j);
            float4 hv = ((const float4*)(g_h + (size_t)sj * HH))[lane];
            acc.x += wj * hv.x; acc.y += wj * hv.y;
            acc.z += wj * hv.z; acc.w += wj * hv.w;
        }
    }
    float wl = __expf(aloop - m);
    {
        float4 hv = ((const float4*)(g_h + (size_t)v * HH))[lane];
        acc.x += wl * hv.x; acc.y += wl * hv.y;
        acc.z += wl * hv.z; acc.w += wl * hv.w;
    }
    float inv = 1.f / (warpSum(dsum) + wl);
    float4 b4 = ((const float4*)bias)[lane];
    float4 o;
    o.x = acc.x * inv + b4.x; o.y = acc.y * inv + b4.y;
    o.z = acc.z * inv + b4.z; o.w = acc.w * inv + b4.w;
    if (!layer2) {
        o.x = fmaxf(o.x, 0.f); o.y = fmaxf(o.y, 0.f);
        o.z = fmaxf(o.z, 0.f); o.w = fmaxf(o.w, 0.f);
        // fused bf16 split for layer-2 GEMM input (row stride HH)
        __nv_bfloat16 h0, h1, h2, h3, m0, m1, m2, m3;
        split1(o.x, h0, m0); split1(o.y, h1, m1);
        split1(o.z, h2, m2); split1(o.w, h3, m3);
        __nv_bfloat162* pAh = (__nv_bfloat162*)(g_Ah + (size_t)v * HH) + lane * 2;
        __nv_bfloat162* pAm = (__nv_bfloat162*)(g_Am + (size_t)v * HH) + lane * 2;
        pAh[0] = __nv_bfloat162(h0, h1); pAh[1] = __nv_bfloat162(h2, h3);
        pAm[0] = __nv_bfloat162(m0, m1); pAm[1] = __nv_bfloat162(m2, m3);
    }
    ((float4*)(g_out + (size_t)v * HH))[lane] = o;
}

// ------------------------- decode (direct atomic fold into out) --------------
__global__ __launch_bounds__(256)
void k_decode_csr(float* __restrict__ out, int half, int n) {
    int warp = (blockIdx.x * blockDim.x + threadIdx.x) >> 5;
    int lane = threadIdx.x & 31;
    if (warp >= n) return;
    int v = warp;
    int r0 = g_rowptr[v], r1 = g_rowptr[v + 1];
    float4 zd = ((const float4*)(g_out + (size_t)v * HH))[lane];
    int i = r0;
    for (; i + 2 <= r1; i += 2) {
        EdgeRec ra = g_rec[i], rb = g_rec[i + 1];
        float4 z0 = ((const float4*)(g_out + (size_t)ra.src * HH))[lane];
        float4 z1 = ((const float4*)(g_out + (size_t)rb.src * HH))[lane];
        float p0 = zd.x * z0.x + zd.y * z0.y + zd.z * z0.z + zd.w * z0.w;
        float p1 = zd.x * z1.x + zd.y * z1.y + zd.z * z1.z + zd.w * z1.w;
#pragma unroll
        for (int o = 16; o; o >>= 1) {
            p0 += __shfl_xor_sync(0xffffffffu, p0, o);
            p1 += __shfl_xor_sync(0xffffffffu, p1, o);
        }
        if (lane == 0) {
            int o0 = ra.eid >= half ? ra.eid - half : ra.eid;
            int o1 = rb.eid >= half ? rb.eid - half : rb.eid;
            atomicAdd(&out[o0], p0);
            atomicAdd(&out[o1], p1);
        }
    }
    if (i < r1) {
        EdgeRec ra = g_rec[i];
        float4 z0 = ((const float4*)(g_out + (size_t)ra.src * HH))[lane];
        float p0 = zd.x * z0.x + zd.y * z0.y + zd.z * z0.z + zd.w * z0.w;
        p0 = warpSum(p0);
        if (lane == 0) {
            int o0 = ra.eid >= half ? ra.eid - half : ra.eid;
            atomicAdd(&out[o0], p0);
        }
    }
}

// ------------------------- launch --------------------------------------------
extern "C" void kernel_launch(void* const* d_in, const int* in_sizes, int n_in,
                              void* d_out, int out_size) {
    const float* x   = (const float*)d_in[0];
    const int*   ei  = (const int*)d_in[1];
    const float* ef  = (const float*)d_in[2];
    const float* W1  = (const float*)d_in[4];
    const float* as1 = (const float*)d_in[5];
    const float* ad1 = (const float*)d_in[6];
    const float* We1 = (const float*)d_in[7];
    const float* ae1 = (const float*)d_in[8];
    const float* b1  = (const float*)d_in[9];
    const float* W2  = (const float*)d_in[10];
    const float* as2 = (const float*)d_in[11];
    const float* ad2 = (const float*)d_in[12];
    const float* We2 = (const float*)d_in[13];
    const float* ae2 = (const float*)d_in[14];
    const float* b2  = (const float*)d_in[15];

    const int E = in_sizes[1] / 2;
    const int N = in_sizes[0] / FIN;
    const int* src = ei;
    const int* dst = ei + E;
    const int half = E / 2;

    cudaFuncSetAttribute(k_gemm, cudaFuncAttributeMaxDynamicSharedMemorySize, GEMM_SMEM);

    // CSR + edge preprocessing
    k_zero<<<(N + 255) / 256, 256>>>(N);
    k_zero_out<<<(half + 255) / 256, 256>>>((float*)d_out, half);
    k_we2<<<16, 256>>>(We1, ae1, We2, ae2);
    k_edge_ae<<<(E + 15) / 16, 256>>>(ef, dst, E);
    k_scan1<<<(N + 1023) / 1024, 1024>>>(N);
    k_scan2<<<1, 64>>>((N + 1023) / 1024);
    k_scan3<<<(N + 255) / 256, 256>>>(N);
    k_fill<<<(E + 255) / 256, 256>>>(src, dst, E);

    // layer 1
    k_splitW<<<(128 * FIN + 255) / 256, 256>>>(W1, FIN);
    k_splitA<<<((N * FIN / 4) + 255) / 256, 256>>>(x, N * FIN / 4);
    k_gemm<<<(N + 127) / 128, 256, GEMM_SMEM>>>(as1, ad1, N, FIN);
    k_aggregate<<<(N * 32 + 255) / 256, 256>>>(b1, N, 0);

    // layer 2 (split of layer-1 output fused into k_aggregate)
    k_splitW<<<(128 * HH + 255) / 256, 256>>>(W2, HH);
    k_gemm<<<(N + 127) / 128, 256, GEMM_SMEM>>>(as2, ad2, N, HH);
    k_aggregate<<<(N * 32 + 255) / 256, 256>>>(b2, N, 1);

    // decode
    k_decode_csr<<<(N * 32 + 255) / 256, 256>>>((float*)d_out, half, N);
}

// round 15
// speedup vs baseline: 1.8242x; 1.0216x over previous
#include <cuda_runtime.h>
#include <cuda_bf16.h>
#include <cstdint>

#define NN   50000
#define EE   800000
#define HH   128
#define FIN  256
#define EDIM 60
#define NEG_SLOPE 0.2f

// ------------------------- scratch ------------------------------------------
struct __align__(16) EdgeRec { int src; int eid; float ae1; float ae2; };

__device__ float g_h[(size_t)NN * HH];
__device__ float g_out[(size_t)NN * HH];
__device__ float g_ae1a[EE];
__device__ float g_ae2a[EE];
__device__ EdgeRec g_rec[EE];
__device__ int   g_deg[NN];
__device__ int   g_cursor[NN];
__device__ int   g_rowptr[NN + 1];
__device__ int   g_bsum[64];
__device__ int   g_boff[64];
__device__ float g_as[NN];
__device__ float g_ad[NN];
__device__ float g_wE1[64];   // padded to 16 float4s
__device__ float g_wE2[64];
// bf16 split operands (A row-major [M][K]; B as Wt[n][k], n=out col)
__device__ __nv_bfloat16 g_Ah[(size_t)NN * FIN];
__device__ __nv_bfloat16 g_Am[(size_t)NN * FIN];
__device__ __nv_bfloat16 g_Bh[128 * FIN];
__device__ __nv_bfloat16 g_Bm[128 * FIN];

// ------------------------- helpers ------------------------------------------
__device__ __forceinline__ float warpSum(float v) {
#pragma unroll
    for (int o = 16; o; o >>= 1) v += __shfl_xor_sync(0xffffffffu, v, o);
    return v;
}
__device__ __forceinline__ float warpMax(float v) {
#pragma unroll
    for (int o = 16; o; o >>= 1) v = fmaxf(v, __shfl_xor_sync(0xffffffffu, v, o));
    return v;
}
__device__ __forceinline__ float lrelu(float a) { return a > 0.f ? a : NEG_SLOPE * a; }

__device__ __forceinline__ uint32_t smem_u32(const void* p) {
    uint32_t a;
    asm("{ .reg .u64 t; cvta.to.shared.u64 t, %1; cvt.u32.u64 %0, t; }" : "=r"(a) : "l"(p));
    return a;
}
__device__ __forceinline__ void cp16(uint32_t dsm, const void* src) {
    asm volatile("cp.async.cg.shared.global [%0], [%1], 16;"
                 :: "r"(dsm), "l"(src) : "memory");
}
#define CP_COMMIT() asm volatile("cp.async.commit_group;" ::: "memory")
#define CP_WAIT0()  asm volatile("cp.async.wait_group 0;" ::: "memory")

// mma.sync m16n8k16 bf16 (baseline PTX, valid at compute_103)
__device__ __forceinline__ void mma_bf16(float* c, const uint32_t* a, const uint32_t* b) {
    asm volatile(
        "mma.sync.aligned.m16n8k16.row.col.f32.bf16.bf16.f32 "
        "{%0,%1,%2,%3}, {%4,%5,%6,%7}, {%8,%9}, {%0,%1,%2,%3};"
        : "+f"(c[0]), "+f"(c[1]), "+f"(c[2]), "+f"(c[3])
        : "r"(a[0]), "r"(a[1]), "r"(a[2]), "r"(a[3]), "r"(b[0]), "r"(b[1]));
}

// ------------------------- init ---------------------------------------------
__global__ void k_zero(int n) {
    int i = blockIdx.x * blockDim.x + threadIdx.x;
    if (i < n) { g_deg[i] = 0; g_cursor[i] = 0; }
}
__global__ void k_zero_out(float* __restrict__ out, int n) {
    int i = blockIdx.x * blockDim.x + threadIdx.x;
    if (i < n) out[i] = 0.f;
}

// ------------------------- parallel scan (3 kernels) -------------------------
__global__ __launch_bounds__(1024)
void k_scan1(int n) {
    __shared__ int wsum[32];
    int i = blockIdx.x * 1024 + threadIdx.x;
    int lane = threadIdx.x & 31, w = threadIdx.x >> 5;
    int v = (i < n) ? g_deg[i] : 0;
    int p = v;
#pragma unroll
    for (int o = 1; o < 32; o <<= 1) {
        int t = __shfl_up_sync(0xffffffffu, p, o);
        if (lane >= o) p += t;
    }
    if (lane == 31) wsum[w] = p;
    __syncthreads();
    if (w == 0) {
        int s = wsum[lane];
#pragma unroll
        for (int o = 1; o < 32; o <<= 1) {
            int t = __shfl_up_sync(0xffffffffu, s, o);
            if (lane >= o) s += t;
        }
        wsum[lane] = s;
    }
    __syncthreads();
    int incl = p + (w > 0 ? wsum[w - 1] : 0);
    if (i < n) g_rowptr[i + 1] = incl;
    if (threadIdx.x == 1023) g_bsum[blockIdx.x] = incl;
}
__global__ void k_scan2(int nb) {
    __shared__ int sm[64];
    int tid = threadIdx.x;
    int v = (tid < nb) ? g_bsum[tid] : 0;
    sm[tid] = v;
    __syncthreads();
#pragma unroll
    for (int off = 1; off < 64; off <<= 1) {
        int t = (tid >= off) ? sm[tid - off] : 0;
        __syncthreads();
        sm[tid] += t;
        __syncthreads();
    }
    g_boff[tid] = sm[tid] - v;   // exclusive
}
__global__ void k_scan3(int n) {
    int i = blockIdx.x * blockDim.x + threadIdx.x;
    if (i == 0) g_rowptr[0] = 0;
    if (i < n) g_rowptr[i + 1] += g_boff[i >> 10];
}

__global__ void k_fill(const int* __restrict__ src, const int* __restrict__ dst, int E) {
    int e = blockIdx.x * blockDim.x + threadIdx.x;
    if (e < E) {
        int d = dst[e];
        int pos = atomicAdd(&g_cursor[d], 1);
        EdgeRec r;
        r.src = src[e]; r.eid = e; r.ae1 = g_ae1a[e]; r.ae2 = g_ae2a[e];
        g_rec[g_rowptr[d] + pos] = r;
    }
}

// ------------------------- wE = We @ a_edge (zero-padded to 64) --------------
__global__ void k_we2(const float* __restrict__ We1, const float* __restrict__ ae1,
                      const float* __restrict__ We2, const float* __restrict__ ae2) {
    int warp = (blockIdx.x * blockDim.x + threadIdx.x) >> 5;
    int lane = threadIdx.x & 31;
    if (warp >= 128) return;
    int which = warp >= 64;
    int r = warp - which * 64;
    float p = 0.f;
    if (r < EDIM) {
        const float* We = which ? We2 : We1;
        const float* ae = which ? ae2 : ae1;
        for (int k = lane; k < HH; k += 32) p += We[r * HH + k] * ae[k];
        p = warpSum(p);
    }
    if (lane == 0) { if (which) g_wE2[r] = p; else g_wE1[r] = p; }
}

// ------------------------- per-edge alpha_e (+deg), smem-staged --------------
// 256 edges per block (E is a multiple of 256: 800000/256 = 3125 blocks).
// Stage 61440 B of ef via 15 coalesced float4 loads/thread (MLP=15), then each
// thread dots one edge's row from smem (stride 15 float4s = conflict-free).
#define EA_SMEM (256 * 15 * 16)
__global__ __launch_bounds__(256)
void k_edge_ae(const float* __restrict__ ef, const int* __restrict__ dst, int E) {
    extern __shared__ float4 sEF[];
    const int tid = threadIdx.x;
    const int e0 = blockIdx.x * 256;
    const float4* ef4 = (const float4*)ef;
    const size_t base = (size_t)e0 * 15;
#pragma unroll
    for (int j = 0; j < 15; j++)
        sEF[tid + j * 256] = ef4[base + tid + j * 256];

    float4 w1[15], w2[15];
#pragma unroll
    for (int j = 0; j < 15; j++) {
        w1[j] = ((const float4*)g_wE1)[j];
        w2[j] = ((const float4*)g_wE2)[j];
    }
    __syncthreads();

    int e = e0 + tid;
    float p1 = 0.f, p2 = 0.f;
#pragma unroll
    for (int j = 0; j < 15; j++) {
        float4 v = sEF[tid * 15 + j];
        p1 += v.x * w1[j].x + v.y * w1[j].y + v.z * w1[j].z + v.w * w1[j].w;
        p2 += v.x * w2[j].x + v.y * w2[j].y + v.z * w2[j].z + v.w * w2[j].w;
    }
    g_ae1a[e] = p1;
    g_ae2a[e] = p2;
    atomicAdd(&g_deg[dst[e]], 1);
}

// ------------------------- bf16 hi/mid split ---------------------------------
__device__ __forceinline__ void split1(float x, __nv_bfloat16& h, __nv_bfloat16& m) {
    h = __float2bfloat16(x);
    m = __float2bfloat16(x - __bfloat162float(h));
}
// layer-1 input x only (layer-2 split is fused into k_aggregate)
__global__ void k_splitA(const float* __restrict__ X, int total4) {
    int i = blockIdx.x * blockDim.x + threadIdx.x;
    if (i >= total4) return;
    float4 v = ((const float4*)X)[i];
    __nv_bfloat16 h0, h1, h2, h3, m0, m1, m2, m3;
    split1(v.x, h0, m0); split1(v.y, h1, m1);
    split1(v.z, h2, m2); split1(v.w, h3, m3);
    ((__nv_bfloat162*)g_Ah)[2 * i]     = __nv_bfloat162(h0, h1);
    ((__nv_bfloat162*)g_Ah)[2 * i + 1] = __nv_bfloat162(h2, h3);
    ((__nv_bfloat162*)g_Am)[2 * i]     = __nv_bfloat162(m0, m1);
    ((__nv_bfloat162*)g_Am)[2 * i + 1] = __nv_bfloat162(m2, m3);
}
// W[K,128] -> Wt[128,K] bf16 hi/mid
__global__ void k_splitW(const float* __restrict__ W, int K) {
    int i = blockIdx.x * blockDim.x + threadIdx.x;
    if (i >= 128 * K) return;
    int nrow = i / K, k = i - nrow * K;
    __nv_bfloat16 h, m;
    split1(W[(size_t)k * 128 + nrow], h, m);
    g_Bh[i] = h;
    g_Bm[i] = m;
}

// ------------------------- bf16-split HMMA GEMM ------------------------------
#define STRIDE 40                      // bf16 elems per smem row (32 + 8 pad = 80B)
#define MATB   (128 * STRIDE * 2)      // 10240 B per matrix per buffer
#define GEMM_SMEM (8 * MATB + 128 * 4 * 4)

__global__ __launch_bounds__(256)
void k_gemm(const float* __restrict__ avs, const float* __restrict__ avd, int M, int K) {
    extern __shared__ char smc[];
    float* sDot = (float*)(smc + 8 * MATB);   // [128][4]
    const int tid = threadIdx.x, lane = tid & 31, wid = tid >> 5;
    const int wm = wid & 3, wn = wid >> 2;
    const int blockRow = blockIdx.x * 128;
    const int tk = (lane & 3) * 2, gq = lane >> 2;

    const __nv_bfloat16* gmat[4] = {g_Ah, g_Am, g_Bh, g_Bm};

    float acc[2][8][4];
#pragma unroll
    for (int a = 0; a < 2; a++)
#pragma unroll
        for (int b = 0; b < 8; b++)
#pragma unroll
            for (int c = 0; c < 4; c++) acc[a][b][c] = 0.f;

    const int nc = K >> 5;
    auto issue = [&](int ch, int buf) {
#pragma unroll
        for (int m = 0; m < 4; m++) {
            const __nv_bfloat16* G = gmat[m];
            const bool isA = m < 2;
#pragma unroll
            for (int it = 0; it < 2; it++) {
                int idx = tid + it * 256;
                int row = idx >> 2, part = idx & 3;
                uint32_t dsm = smem_u32(smc + (buf * 4 + m) * MATB + row * 80 + part * 16);
                int grow = isA ? min(blockRow + row, M - 1) : row;
                const __nv_bfloat16* src = G + (size_t)grow * K + ch * 32 + part * 8;
                cp16(dsm, src);
            }
        }
    };

    issue(0, 0);
    CP_COMMIT();

    for (int c = 0; c < nc; c++) {
        CP_WAIT0();
        __syncthreads();
        if (c + 1 < nc) { issue(c + 1, (c + 1) & 1); CP_COMMIT(); }
        const int buf = c & 1;
        const __nv_bfloat16* Ah = (const __nv_bfloat16*)(smc + (buf * 4 + 0) * MATB);
        const __nv_bfloat16* Am = (const __nv_bfloat16*)(smc + (buf * 4 + 1) * MATB);
        const __nv_bfloat16* Bh = (const __nv_bfloat16*)(smc + (buf * 4 + 2) * MATB);
        const __nv_bfloat16* Bm = (const __nv_bfloat16*)(smc + (buf * 4 + 3) * MATB);
#pragma unroll
        for (int kk = 0; kk < 32; kk += 16) {
            uint32_t ah[2][4], am[2][4];
#pragma unroll
            for (int mi = 0; mi < 2; mi++) {
                int r0 = wm * 32 + mi * 16 + gq;
                ah[mi][0] = *(const uint32_t*)(Ah + r0 * STRIDE + kk + tk);
                ah[mi][1] = *(const uint32_t*)(Ah + (r0 + 8) * STRIDE + kk + tk);
                ah[mi][2] = *(const uint32_t*)(Ah + r0 * STRIDE + kk + 8 + tk);
                ah[mi][3] = *(const uint32_t*)(Ah + (r0 + 8) * STRIDE + kk + 8 + tk);
                am[mi][0] = *(const uint32_t*)(Am + r0 * STRIDE + kk + tk);
                am[mi][1] = *(const uint32_t*)(Am + (r0 + 8) * STRIDE + kk + tk);
                am[mi][2] = *(const uint32_t*)(Am + r0 * STRIDE + kk + 8 + tk);
                am[mi][3] = *(const uint32_t*)(Am + (r0 + 8) * STRIDE + kk + 8 + tk);
            }
            uint32_t bh[8][2], bm[8][2];
#pragma unroll
            for (int ni = 0; ni < 8; ni++) {
                int n0 = wn * 64 + ni * 8 + gq;
                bh[ni][0] = *(const uint32_t*)(Bh + n0 * STRIDE + kk + tk);
                bh[ni][1] = *(const uint32_t*)(Bh + n0 * STRIDE + kk + 8 + tk);
                bm[ni][0] = *(const uint32_t*)(Bm + n0 * STRIDE + kk + tk);
                bm[ni][1] = *(const uint32_t*)(Bm + n0 * STRIDE + kk + 8 + tk);
            }
#pragma unroll
            for (int mi = 0; mi < 2; mi++)
#pragma unroll
                for (int ni = 0; ni < 8; ni++) {
                    mma_bf16(acc[mi][ni], ah[mi], bh[ni]);
                    mma_bf16(acc[mi][ni], ah[mi], bm[ni]);
                    mma_bf16(acc[mi][ni], am[mi], bh[ni]);
                }
        }
    }
    __syncthreads();

    // epilogue: store C rows + fused a_src/a_dst dots
#pragma unroll
    for (int mi = 0; mi < 2; mi++) {
        int rloc = wm * 32 + mi * 16 + gq;
        int gr = blockRow + rloc;
        float psA = 0.f, pdA = 0.f, psB = 0.f, pdB = 0.f;
#pragma unroll
        for (int ni = 0; ni < 8; ni++) {
            int col = wn * 64 + ni * 8 + tk;
            float c0 = acc[mi][ni][0], c1 = acc[mi][ni][1];
            float c2 = acc[mi][ni][2], c3 = acc[mi][ni][3];
            if (gr < M) { float2 v = make_float2(c0, c1);
                          *(float2*)(g_h + (size_t)gr * 128 + col) = v; }
            if (gr + 8 < M) { float2 v = make_float2(c2, c3);
                              *(float2*)(g_h + (size_t)(gr + 8) * 128 + col) = v; }
            float s0 = avs[col], s1 = avs[col + 1];
            float d0 = avd[col], d1 = avd[col + 1];
            psA += c0 * s0 + c1 * s1; pdA += c0 * d0 + c1 * d1;
            psB += c2 * s0 + c3 * s1; pdB += c2 * d0 + c3 * d1;
        }
#pragma unroll
        for (int o = 1; o <= 2; o <<= 1) {
            psA += __shfl_xor_sync(0xffffffffu, psA, o);
            pdA += __shfl_xor_sync(0xffffffffu, pdA, o);
            psB += __shfl_xor_sync(0xffffffffu, psB, o);
            pdB += __shfl_xor_sync(0xffffffffu, pdB, o);
        }
        if ((lane & 3) == 0) {
            sDot[rloc * 4 + wn] = psA;       sDot[rloc * 4 + 2 + wn] = pdA;
            sDot[(rloc + 8) * 4 + wn] = psB; sDot[(rloc + 8) * 4 + 2 + wn] = pdB;
        }
    }
    __syncthreads();
    if (tid < 128) {
        int gr = blockRow + tid;
        if (gr < M) {
            g_as[gr] = sDot[tid * 4] + sDot[tid * 4 + 1];
            g_ad[gr] = sDot[tid * 4 + 2] + sDot[tid * 4 + 3];
        }
    }
}

// ------------------------- fused softmax + aggregate -------------------------
// pass 1 computes both the max and the sum of incoming ae (for the self-loop
// attr), eliminating the former g_sumae atomics. Layer 1 additionally writes
// the bf16 split of its output into g_Ah/g_Am (feeds the layer-2 GEMM).
__global__ __launch_bounds__(256)
void k_aggregate(const float* __restrict__ bias, int n, int layer2) {
    int warp = (blockIdx.x * blockDim.x + threadIdx.x) >> 5;
    int lane = threadIdx.x & 31;
    if (warp >= n) return;
    int v = warp;
    int r0 = g_rowptr[v], r1 = g_rowptr[v + 1];
    int deg = r1 - r0;
    float adv = g_ad[v];

    float m = -1e30f;
    float sae = 0.f;
    for (int i = r0 + lane; i < r1; i += 32) {
        EdgeRec r = g_rec[i];
        float ae = layer2 ? r.ae2 : r.ae1;
        sae += ae;
        m = fmaxf(m, lrelu(g_as[r.src] + adv + ae));
    }
    sae = warpSum(sae);
    float aloop = lrelu(g_as[v] + adv + sae / (float)(deg > 0 ? deg : 1));
    m = fmaxf(warpMax(m), aloop);

    float4 acc = make_float4(0.f, 0.f, 0.f, 0.f);
    float dsum = 0.f;
    for (int c0 = r0; c0 < r1; c0 += 32) {
        int i = c0 + lane;
        float w = 0.f;
        int s = 0;
        if (i < r1) {
            EdgeRec r = g_rec[i];
            s = r.src;
            float ae = layer2 ? r.ae2 : r.ae1;
            w = __expf(lrelu(g_as[s] + adv + ae) - m);
        }
        dsum += w;
        int cnt = min(32, r1 - c0);
        int j = 0;
        for (; j + 4 <= cnt; j += 4) {
            float w0 = __shfl_sync(0xffffffffu, w, j);
            float w1 = __shfl_sync(0xffffffffu, w, j + 1);
            float w2 = __shfl_sync(0xffffffffu, w, j + 2);
            float w3 = __shfl_sync(0xffffffffu, w, j + 3);
            int s0 = __shfl_sync(0xffffffffu, s, j);
            int s1 = __shfl_sync(0xffffffffu, s, j + 1);
            int s2 = __shfl_sync(0xffffffffu, s, j + 2);
            int s3 = __shfl_sync(0xffffffffu, s, j + 3);
            float4 h0 = ((const float4*)(g_h + (size_t)s0 * HH))[lane];
            float4 h1 = ((const float4*)(g_h + (size_t)s1 * HH))[lane];
            float4 h2 = ((const float4*)(g_h + (size_t)s2 * HH))[lane];
            float4 h3 = ((const float4*)(g_h + (size_t)s3 * HH))[lane];
            acc.x += w0 * h0.x + w1 * h1.x + w2 * h2.x + w3 * h3.x;
            acc.y += w0 * h0.y + w1 * h1.y + w2 * h2.y + w3 * h3.y;
            acc.z += w0 * h0.z + w1 * h1.z + w2 * h2.z + w3 * h3.z;
            acc.w += w0 * h0.w + w1 * h1.w + w2 * h2.w + w3 * h3.w;
        }
        for (; j < cnt; j++) {
            float wj = __shfl_sync(0xffffffffu, w, j);
            int sj = __shfl_sync(0xffffffffu, s, j);
            float4 hv = ((const float4*)(g_h + (size_t)sj * HH))[lane];
            acc.x += wj * hv.x; acc.y += wj * hv.y;
            acc.z += wj * hv.z; acc.w += wj * hv.w;
        }
    }
    float wl = __expf(aloop - m);
    {
        float4 hv = ((const float4*)(g_h + (size_t)v * HH))[lane];
        acc.x += wl * hv.x; acc.y += wl * hv.y;
        acc.z += wl * hv.z; acc.w += wl * hv.w;
    }
    float inv = 1.f / (warpSum(dsum) + wl);
    float4 b4 = ((const float4*)bias)[lane];
    float4 o;
    o.x = acc.x * inv + b4.x; o.y = acc.y * inv + b4.y;
    o.z = acc.z * inv + b4.z; o.w = acc.w * inv + b4.w;
    if (!layer2) {
        o.x = fmaxf(o.x, 0.f); o.y = fmaxf(o.y, 0.f);
        o.z = fmaxf(o.z, 0.f); o.w = fmaxf(o.w, 0.f);
        // fused bf16 split for layer-2 GEMM input (row stride HH)
        __nv_bfloat16 h0, h1, h2, h3, m0, m1, m2, m3;
        split1(o.x, h0, m0); split1(o.y, h1, m1);
        split1(o.z, h2, m2); split1(o.w, h3, m3);
        __nv_bfloat162* pAh = (__nv_bfloat162*)(g_Ah + (size_t)v * HH) + lane * 2;
        __nv_bfloat162* pAm = (__nv_bfloat162*)(g_Am + (size_t)v * HH) + lane * 2;
        pAh[0] = __nv_bfloat162(h0, h1); pAh[1] = __nv_bfloat162(h2, h3);
        pAm[0] = __nv_bfloat162(m0, m1); pAm[1] = __nv_bfloat162(m2, m3);
    }
    ((float4*)(g_out + (size_t)v * HH))[lane] = o;
}

// ------------------------- decode (direct atomic fold into out) --------------
__global__ __launch_bounds__(256)
void k_decode_csr(float* __restrict__ out, int half, int n) {
    int warp = (blockIdx.x * blockDim.x + threadIdx.x) >> 5;
    int lane = threadIdx.x & 31;
    if (warp >= n) return;
    int v = warp;
    int r0 = g_rowptr[v], r1 = g_rowptr[v + 1];
    float4 zd = ((const float4*)(g_out + (size_t)v * HH))[lane];
    int i = r0;
    for (; i + 2 <= r1; i += 2) {
        EdgeRec ra = g_rec[i], rb = g_rec[i + 1];
        float4 z0 = ((const float4*)(g_out + (size_t)ra.src * HH))[lane];
        float4 z1 = ((const float4*)(g_out + (size_t)rb.src * HH))[lane];
        float p0 = zd.x * z0.x + zd.y * z0.y + zd.z * z0.z + zd.w * z0.w;
        float p1 = zd.x * z1.x + zd.y * z1.y + zd.z * z1.z + zd.w * z1.w;
#pragma unroll
        for (int o = 16; o; o >>= 1) {
            p0 += __shfl_xor_sync(0xffffffffu, p0, o);
            p1 += __shfl_xor_sync(0xffffffffu, p1, o);
        }
        if (lane == 0) {
            int o0 = ra.eid >= half ? ra.eid - half : ra.eid;
            int o1 = rb.eid >= half ? rb.eid - half : rb.eid;
            atomicAdd(&out[o0], p0);
            atomicAdd(&out[o1], p1);
        }
    }
    if (i < r1) {
        EdgeRec ra = g_rec[i];
        float4 z0 = ((const float4*)(g_out + (size_t)ra.src * HH))[lane];
        float p0 = zd.x * z0.x + zd.y * z0.y + zd.z * z0.z + zd.w * z0.w;
        p0 = warpSum(p0);
        if (lane == 0) {
            int o0 = ra.eid >= half ? ra.eid - half : ra.eid;
            atomicAdd(&out[o0], p0);
        }
    }
}

// ------------------------- launch --------------------------------------------
extern "C" void kernel_launch(void* const* d_in, const int* in_sizes, int n_in,
                              void* d_out, int out_size) {
    const float* x   = (const float*)d_in[0];
    const int*   ei  = (const int*)d_in[1];
    const float* ef  = (const float*)d_in[2];
    const float* W1  = (const float*)d_in[4];
    const float* as1 = (const float*)d_in[5];
    const float* ad1 = (const float*)d_in[6];
    const float* We1 = (const float*)d_in[7];
    const float* ae1 = (const float*)d_in[8];
    const float* b1  = (const float*)d_in[9];
    const float* W2  = (const float*)d_in[10];
    const float* as2 = (const float*)d_in[11];
    const float* ad2 = (const float*)d_in[12];
    const float* We2 = (const float*)d_in[13];
    const float* ae2 = (const float*)d_in[14];
    const float* b2  = (const float*)d_in[15];

    const int E = in_sizes[1] / 2;
    const int N = in_sizes[0] / FIN;
    const int* src = ei;
    const int* dst = ei + E;
    const int half = E / 2;

    cudaFuncSetAttribute(k_gemm, cudaFuncAttributeMaxDynamicSharedMemorySize, GEMM_SMEM);
    cudaFuncSetAttribute(k_edge_ae, cudaFuncAttributeMaxDynamicSharedMemorySize, EA_SMEM);

    // CSR + edge preprocessing
    k_zero<<<(N + 255) / 256, 256>>>(N);
    k_zero_out<<<(half + 255) / 256, 256>>>((float*)d_out, half);
    k_we2<<<16, 256>>>(We1, ae1, We2, ae2);
    k_edge_ae<<<E / 256, 256, EA_SMEM>>>(ef, dst, E);
    k_scan1<<<(N + 1023) / 1024, 1024>>>(N);
    k_scan2<<<1, 64>>>((N + 1023) / 1024);
    k_scan3<<<(N + 255) / 256, 256>>>(N);
    k_fill<<<(E + 255) / 256, 256>>>(src, dst, E);

    // layer 1
    k_splitW<<<(128 * FIN + 255) / 256, 256>>>(W1, FIN);
    k_splitA<<<((N * FIN / 4) + 255) / 256, 256>>>(x, N * FIN / 4);
    k_gemm<<<(N + 127) / 128, 256, GEMM_SMEM>>>(as1, ad1, N, FIN);
    k_aggregate<<<(N * 32 + 255) / 256, 256>>>(b1, N, 0);

    // layer 2 (split of layer-1 output fused into k_aggregate)
    k_splitW<<<(128 * HH + 255) / 256, 256>>>(W2, HH);
    k_gemm<<<(N + 127) / 128, 256, GEMM_SMEM>>>(as2, ad2, N, HH);
    k_aggregate<<<(N * 32 + 255) / 256, 256>>>(b2, N, 1);

    // decode
    k_decode_csr<<<(N * 32 + 255) / 256, 256>>>((float*)d_out, half, N);
}

// round 17
// speedup vs baseline: 1.8368x; 1.0069x over previous
#include <cuda_runtime.h>
#include <cuda_bf16.h>
#include <cstdint>

#define NN   50000
#define EE   800000
#define HH   128
#define FIN  256
#define EDIM 60
#define NEG_SLOPE 0.2f

// ------------------------- scratch ------------------------------------------
struct __align__(16) EdgeRec { int src; int eid; float ae1; float ae2; };

__device__ float g_h[(size_t)NN * HH];
__device__ float g_out[(size_t)NN * HH];
__device__ float g_ae1a[EE];
__device__ float g_ae2a[EE];
__device__ EdgeRec g_rec[EE];
__device__ int   g_deg[NN];
__device__ int   g_cursor[NN];
__device__ int   g_rowptr[NN + 1];
__device__ int   g_bsum[64];
__device__ int   g_boff[64];
__device__ float g_as[NN];
__device__ float g_ad[NN];
__device__ float g_wE1[64];   // padded to 16 float4s
__device__ float g_wE2[64];
// bf16 split operands (A row-major [M][K]; B as Wt[n][k], n=out col)
__device__ __nv_bfloat16 g_Ah[(size_t)NN * FIN];
__device__ __nv_bfloat16 g_Am[(size_t)NN * FIN];
__device__ __nv_bfloat16 g_Bh[128 * FIN];
__device__ __nv_bfloat16 g_Bm[128 * FIN];

// ------------------------- helpers ------------------------------------------
__device__ __forceinline__ float warpSum(float v) {
#pragma unroll
    for (int o = 16; o; o >>= 1) v += __shfl_xor_sync(0xffffffffu, v, o);
    return v;
}
__device__ __forceinline__ float warpMax(float v) {
#pragma unroll
    for (int o = 16; o; o >>= 1) v = fmaxf(v, __shfl_xor_sync(0xffffffffu, v, o));
    return v;
}
__device__ __forceinline__ float lrelu(float a) { return a > 0.f ? a : NEG_SLOPE * a; }

__device__ __forceinline__ uint32_t smem_u32(const void* p) {
    uint32_t a;
    asm("{ .reg .u64 t; cvta.to.shared.u64 t, %1; cvt.u32.u64 %0, t; }" : "=r"(a) : "l"(p));
    return a;
}
__device__ __forceinline__ void cp16(uint32_t dsm, const void* src) {
    asm volatile("cp.async.cg.shared.global [%0], [%1], 16;"
                 :: "r"(dsm), "l"(src) : "memory");
}
#define CP_COMMIT() asm volatile("cp.async.commit_group;" ::: "memory")
#define CP_WAIT0()  asm volatile("cp.async.wait_group 0;" ::: "memory")

// mma.sync m16n8k16 bf16 (baseline PTX, valid at compute_103)
__device__ __forceinline__ void mma_bf16(float* c, const uint32_t* a, const uint32_t* b) {
    asm volatile(
        "mma.sync.aligned.m16n8k16.row.col.f32.bf16.bf16.f32 "
        "{%0,%1,%2,%3}, {%4,%5,%6,%7}, {%8,%9}, {%0,%1,%2,%3};"
        : "+f"(c[0]), "+f"(c[1]), "+f"(c[2]), "+f"(c[3])
        : "r"(a[0]), "r"(a[1]), "r"(a[2]), "r"(a[3]), "r"(b[0]), "r"(b[1]));
}

// ------------------------- init ---------------------------------------------
__global__ void k_zero(int n) {
    int i = blockIdx.x * blockDim.x + threadIdx.x;
    if (i < n) { g_deg[i] = 0; g_cursor[i] = 0; }
}
__global__ void k_zero_out(float* __restrict__ out, int n) {
    int i = blockIdx.x * blockDim.x + threadIdx.x;
    if (i < n) out[i] = 0.f;
}

// ------------------------- parallel scan (3 kernels) -------------------------
__global__ __launch_bounds__(1024)
void k_scan1(int n) {
    __shared__ int wsum[32];
    int i = blockIdx.x * 1024 + threadIdx.x;
    int lane = threadIdx.x & 31, w = threadIdx.x >> 5;
    int v = (i < n) ? g_deg[i] : 0;
    int p = v;
#pragma unroll
    for (int o = 1; o < 32; o <<= 1) {
        int t = __shfl_up_sync(0xffffffffu, p, o);
        if (lane >= o) p += t;
    }
    if (lane == 31) wsum[w] = p;
    __syncthreads();
    if (w == 0) {
        int s = wsum[lane];
#pragma unroll
        for (int o = 1; o < 32; o <<= 1) {
            int t = __shfl_up_sync(0xffffffffu, s, o);
            if (lane >= o) s += t;
        }
        wsum[lane] = s;
    }
    __syncthreads();
    int incl = p + (w > 0 ? wsum[w - 1] : 0);
    if (i < n) g_rowptr[i + 1] = incl;
    if (threadIdx.x == 1023) g_bsum[blockIdx.x] = incl;
}
__global__ void k_scan2(int nb) {
    __shared__ int sm[64];
    int tid = threadIdx.x;
    int v = (tid < nb) ? g_bsum[tid] : 0;
    sm[tid] = v;
    __syncthreads();
#pragma unroll
    for (int off = 1; off < 64; off <<= 1) {
        int t = (tid >= off) ? sm[tid - off] : 0;
        __syncthreads();
        sm[tid] += t;
        __syncthreads();
    }
    g_boff[tid] = sm[tid] - v;   // exclusive
}
__global__ void k_scan3(int n) {
    int i = blockIdx.x * blockDim.x + threadIdx.x;
    if (i == 0) g_rowptr[0] = 0;
    if (i < n) g_rowptr[i + 1] += g_boff[i >> 10];
}

__global__ void k_fill(const int* __restrict__ src, const int* __restrict__ dst, int E) {
    int e = blockIdx.x * blockDim.x + threadIdx.x;
    if (e < E) {
        int d = dst[e];
        int pos = atomicAdd(&g_cursor[d], 1);
        EdgeRec r;
        r.src = src[e]; r.eid = e; r.ae1 = g_ae1a[e]; r.ae2 = g_ae2a[e];
        g_rec[g_rowptr[d] + pos] = r;
    }
}

// ------------------------- wE = We @ a_edge (zero-padded to 64) --------------
__global__ void k_we2(const float* __restrict__ We1, const float* __restrict__ ae1,
                      const float* __restrict__ We2, const float* __restrict__ ae2) {
    int warp = (blockIdx.x * blockDim.x + threadIdx.x) >> 5;
    int lane = threadIdx.x & 31;
    if (warp >= 128) return;
    int which = warp >= 64;
    int r = warp - which * 64;
    float p = 0.f;
    if (r < EDIM) {
        const float* We = which ? We2 : We1;
        const float* ae = which ? ae2 : ae1;
        for (int k = lane; k < HH; k += 32) p += We[r * HH + k] * ae[k];
        p = warpSum(p);
    }
    if (lane == 0) { if (which) g_wE2[r] = p; else g_wE1[r] = p; }
}

// ------------------------- per-edge alpha_e (+deg), smem-staged --------------
// 256 edges per block (E = 800000 = 3125 * 256, no tail). Stage 61440 B of ef
// via 15 coalesced float4 loads/thread (MLP=15); wE vectors live in SMEM
// (broadcast reads) to keep register count low -> high occupancy.
#define EA_SMEM (256 * 15 * 16 + 2 * 16 * 16)
__global__ __launch_bounds__(256)
void k_edge_ae(const float* __restrict__ ef, const int* __restrict__ dst, int E) {
    extern __shared__ float4 sEF[];
    float4* sW1 = sEF + 256 * 15;
    float4* sW2 = sW1 + 16;
    const int tid = threadIdx.x;
    const int e0 = blockIdx.x * 256;
    const float4* ef4 = (const float4*)ef;
    const size_t base = (size_t)e0 * 15;
#pragma unroll
    for (int j = 0; j < 15; j++)
        sEF[tid + j * 256] = ef4[base + tid + j * 256];
    if (tid < 16) {
        sW1[tid] = ((const float4*)g_wE1)[tid];
        sW2[tid] = ((const float4*)g_wE2)[tid];
    }
    __syncthreads();

    int e = e0 + tid;
    float a1 = 0.f, a2 = 0.f, b1 = 0.f, b2 = 0.f;
#pragma unroll
    for (int j = 0; j < 15; j += 2) {
        float4 v = sEF[tid * 15 + j];
        float4 w1 = sW1[j], w2 = sW2[j];
        a1 += v.x * w1.x + v.y * w1.y + v.z * w1.z + v.w * w1.w;
        a2 += v.x * w2.x + v.y * w2.y + v.z * w2.z + v.w * w2.w;
        if (j + 1 < 15) {
            float4 u = sEF[tid * 15 + j + 1];
            float4 x1 = sW1[j + 1], x2 = sW2[j + 1];
            b1 += u.x * x1.x + u.y * x1.y + u.z * x1.z + u.w * x1.w;
            b2 += u.x * x2.x + u.y * x2.y + u.z * x2.z + u.w * x2.w;
        }
    }
    g_ae1a[e] = a1 + b1;
    g_ae2a[e] = a2 + b2;
    atomicAdd(&g_deg[dst[e]], 1);
}

// ------------------------- bf16 hi/mid split ---------------------------------
__device__ __forceinline__ void split1(float x, __nv_bfloat16& h, __nv_bfloat16& m) {
    h = __float2bfloat16(x);
    m = __float2bfloat16(x - __bfloat162float(h));
}
// layer-1 input x only (layer-2 split is fused into k_aggregate)
__global__ void k_splitA(const float* __restrict__ X, int total4) {
    int i = blockIdx.x * blockDim.x + threadIdx.x;
    if (i >= total4) return;
    float4 v = ((const float4*)X)[i];
    __nv_bfloat16 h0, h1, h2, h3, m0, m1, m2, m3;
    split1(v.x, h0, m0); split1(v.y, h1, m1);
    split1(v.z, h2, m2); split1(v.w, h3, m3);
    ((__nv_bfloat162*)g_Ah)[2 * i]     = __nv_bfloat162(h0, h1);
    ((__nv_bfloat162*)g_Ah)[2 * i + 1] = __nv_bfloat162(h2, h3);
    ((__nv_bfloat162*)g_Am)[2 * i]     = __nv_bfloat162(m0, m1);
    ((__nv_bfloat162*)g_Am)[2 * i + 1] = __nv_bfloat162(m2, m3);
}
// W[K,128] -> Wt[128,K] bf16 hi/mid
__global__ void k_splitW(const float* __restrict__ W, int K) {
    int i = blockIdx.x * blockDim.x + threadIdx.x;
    if (i >= 128 * K) return;
    int nrow = i / K, k = i - nrow * K;
    __nv_bfloat16 h, m;
    split1(W[(size_t)k * 128 + nrow], h, m);
    g_Bh[i] = h;
    g_Bm[i] = m;
}

// ------------------------- bf16-split HMMA GEMM ------------------------------
#define STRIDE 40                      // bf16 elems per smem row (32 + 8 pad = 80B)
#define MATB   (128 * STRIDE * 2)      // 10240 B per matrix per buffer
#define GEMM_SMEM (8 * MATB + 128 * 4 * 4)

__global__ __launch_bounds__(256)
void k_gemm(const float* __restrict__ avs, const float* __restrict__ avd, int M, int K) {
    extern __shared__ char smc[];
    float* sDot = (float*)(smc + 8 * MATB);   // [128][4]
    const int tid = threadIdx.x, lane = tid & 31, wid = tid >> 5;
    const int wm = wid & 3, wn = wid >> 2;
    const int blockRow = blockIdx.x * 128;
    const int tk = (lane & 3) * 2, gq = lane >> 2;

    const __nv_bfloat16* gmat[4] = {g_Ah, g_Am, g_Bh, g_Bm};

    float acc[2][8][4];
#pragma unroll
    for (int a = 0; a < 2; a++)
#pragma unroll
        for (int b = 0; b < 8; b++)
#pragma unroll
            for (int c = 0; c < 4; c++) acc[a][b][c] = 0.f;

    const int nc = K >> 5;
    auto issue = [&](int ch, int buf) {
#pragma unroll
        for (int m = 0; m < 4; m++) {
            const __nv_bfloat16* G = gmat[m];
            const bool isA = m < 2;
#pragma unroll
            for (int it = 0; it < 2; it++) {
                int idx = tid + it * 256;
                int row = idx >> 2, part = idx & 3;
                uint32_t dsm = smem_u32(smc + (buf * 4 + m) * MATB + row * 80 + part * 16);
                int grow = isA ? min(blockRow + row, M - 1) : row;
                const __nv_bfloat16* src = G + (size_t)grow * K + ch * 32 + part * 8;
                cp16(dsm, src);
            }
        }
    };

    issue(0, 0);
    CP_COMMIT();

    for (int c = 0; c < nc; c++) {
        CP_WAIT0();
        __syncthreads();
        if (c + 1 < nc) { issue(c + 1, (c + 1) & 1); CP_COMMIT(); }
        const int buf = c & 1;
        const __nv_bfloat16* Ah = (const __nv_bfloat16*)(smc + (buf * 4 + 0) * MATB);
        const __nv_bfloat16* Am = (const __nv_bfloat16*)(smc + (buf * 4 + 1) * MATB);
        const __nv_bfloat16* Bh = (const __nv_bfloat16*)(smc + (buf * 4 + 2) * MATB);
        const __nv_bfloat16* Bm = (const __nv_bfloat16*)(smc + (buf * 4 + 3) * MATB);
#pragma unroll
        for (int kk = 0; kk < 32; kk += 16) {
            uint32_t ah[2][4], am[2][4];
#pragma unroll
            for (int mi = 0; mi < 2; mi++) {
                int r0 = wm * 32 + mi * 16 + gq;
                ah[mi][0] = *(const uint32_t*)(Ah + r0 * STRIDE + kk + tk);
                ah[mi][1] = *(const uint32_t*)(Ah + (r0 + 8) * STRIDE + kk + tk);
                ah[mi][2] = *(const uint32_t*)(Ah + r0 * STRIDE + kk + 8 + tk);
                ah[mi][3] = *(const uint32_t*)(Ah + (r0 + 8) * STRIDE + kk + 8 + tk);
                am[mi][0] = *(const uint32_t*)(Am + r0 * STRIDE + kk + tk);
                am[mi][1] = *(const uint32_t*)(Am + (r0 + 8) * STRIDE + kk + tk);
                am[mi][2] = *(const uint32_t*)(Am + r0 * STRIDE + kk + 8 + tk);
                am[mi][3] = *(const uint32_t*)(Am + (r0 + 8) * STRIDE + kk + 8 + tk);
            }
            uint32_t bh[8][2], bm[8][2];
#pragma unroll
            for (int ni = 0; ni < 8; ni++) {
                int n0 = wn * 64 + ni * 8 + gq;
                bh[ni][0] = *(const uint32_t*)(Bh + n0 * STRIDE + kk + tk);
                bh[ni][1] = *(const uint32_t*)(Bh + n0 * STRIDE + kk + 8 + tk);
                bm[ni][0] = *(const uint32_t*)(Bm + n0 * STRIDE + kk + tk);
                bm[ni][1] = *(const uint32_t*)(Bm + n0 * STRIDE + kk + 8 + tk);
            }
#pragma unroll
            for (int mi = 0; mi < 2; mi++)
#pragma unroll
                for (int ni = 0; ni < 8; ni++) {
                    mma_bf16(acc[mi][ni], ah[mi], bh[ni]);
                    mma_bf16(acc[mi][ni], ah[mi], bm[ni]);
                    mma_bf16(acc[mi][ni], am[mi], bh[ni]);
                }
        }
    }
    __syncthreads();

    // epilogue: store C rows + fused a_src/a_dst dots
#pragma unroll
    for (int mi = 0; mi < 2; mi++) {
        int rloc = wm * 32 + mi * 16 + gq;
        int gr = blockRow + rloc;
        float psA = 0.f, pdA = 0.f, psB = 0.f, pdB = 0.f;
#pragma unroll
        for (int ni = 0; ni < 8; ni++) {
            int col = wn * 64 + ni * 8 + tk;
            float c0 = acc[mi][ni][0], c1 = acc[mi][ni][1];
            float c2 = acc[mi][ni][2], c3 = acc[mi][ni][3];
            if (gr < M) { float2 v = make_float2(c0, c1);
                          *(float2*)(g_h + (size_t)gr * 128 + col) = v; }
            if (gr + 8 < M) { float2 v = make_float2(c2, c3);
                              *(float2*)(g_h + (size_t)(gr + 8) * 128 + col) = v; }
            float s0 = avs[col], s1 = avs[col + 1];
            float d0 = avd[col], d1 = avd[col + 1];
            psA += c0 * s0 + c1 * s1; pdA += c0 * d0 + c1 * d1;
            psB += c2 * s0 + c3 * s1; pdB += c2 * d0 + c3 * d1;
        }
#pragma unroll
        for (int o = 1; o <= 2; o <<= 1) {
            psA += __shfl_xor_sync(0xffffffffu, psA, o);
            pdA += __shfl_xor_sync(0xffffffffu, pdA, o);
            psB += __shfl_xor_sync(0xffffffffu, psB, o);
            pdB += __shfl_xor_sync(0xffffffffu, pdB, o);
        }
        if ((lane & 3) == 0) {
            sDot[rloc * 4 + wn] = psA;       sDot[rloc * 4 + 2 + wn] = pdA;
            sDot[(rloc + 8) * 4 + wn] = psB; sDot[(rloc + 8) * 4 + 2 + wn] = pdB;
        }
    }
    __syncthreads();
    if (tid < 128) {
        int gr = blockRow + tid;
        if (gr < M) {
            g_as[gr] = sDot[tid * 4] + sDot[tid * 4 + 1];
            g_ad[gr] = sDot[tid * 4 + 2] + sDot[tid * 4 + 3];
        }
    }
}

// ------------------------- fused softmax + aggregate -------------------------
// pass 1 computes both the max and the sum of incoming ae (self-loop attr),
// eliminating sumae atomics. Layer 1 additionally writes the bf16 split of its
// output into g_Ah/g_Am (feeds the layer-2 GEMM).
__global__ __launch_bounds__(256)
void k_aggregate(const float* __restrict__ bias, int n, int layer2) {
    int warp = (blockIdx.x * blockDim.x + threadIdx.x) >> 5;
    int lane = threadIdx.x & 31;
    if (warp >= n) return;
    int v = warp;
    int r0 = g_rowptr[v], r1 = g_rowptr[v + 1];
    int deg = r1 - r0;
    float adv = g_ad[v];

    float m = -1e30f;
    float sae = 0.f;
    for (int i = r0 + lane; i < r1; i += 32) {
        EdgeRec r = g_rec[i];
        float ae = layer2 ? r.ae2 : r.ae1;
        sae += ae;
        m = fmaxf(m, lrelu(g_as[r.src] + adv + ae));
    }
    sae = warpSum(sae);
    float aloop = lrelu(g_as[v] + adv + sae / (float)(deg > 0 ? deg : 1));
    m = fmaxf(warpMax(m), aloop);

    float4 acc = make_float4(0.f, 0.f, 0.f, 0.f);
    float dsum = 0.f;
    for (int c0 = r0; c0 < r1; c0 += 32) {
        int i = c0 + lane;
        float w = 0.f;
        int s = 0;
        if (i < r1) {
            EdgeRec r = g_rec[i];
            s = r.src;
            float ae = layer2 ? r.ae2 : r.ae1;
            w = __expf(lrelu(g_as[s] + adv + ae) - m);
        }
        dsum += w;
        int cnt = min(32, r1 - c0);
        int j = 0;
        for (; j + 4 <= cnt; j += 4) {
            float w0 = __shfl_sync(0xffffffffu, w, j);
            float w1 = __shfl_sync(0xffffffffu, w, j + 1);
            float w2 = __shfl_sync(0xffffffffu, w, j + 2);
            float w3 = __shfl_sync(0xffffffffu, w, j + 3);
            int s0 = __shfl_sync(0xffffffffu, s, j);
            int s1 = __shfl_sync(0xffffffffu, s, j + 1);
            int s2 = __shfl_sync(0xffffffffu, s, j + 2);
            int s3 = __shfl_sync(0xffffffffu, s, j + 3);
            float4 h0 = ((const float4*)(g_h + (size_t)s0 * HH))[lane];
            float4 h1 = ((const float4*)(g_h + (size_t)s1 * HH))[lane];
            float4 h2 = ((const float4*)(g_h + (size_t)s2 * HH))[lane];
            float4 h3 = ((const float4*)(g_h + (size_t)s3 * HH))[lane];
            acc.x += w0 * h0.x + w1 * h1.x + w2 * h2.x + w3 * h3.x;
            acc.y += w0 * h0.y + w1 * h1.y + w2 * h2.y + w3 * h3.y;
            acc.z += w0 * h0.z + w1 * h1.z + w2 * h2.z + w3 * h3.z;
            acc.w += w0 * h0.w + w1 * h1.w + w2 * h2.w + w3 * h3.w;
        }
        for (; j < cnt; j++) {
            float wj = __shfl_sync(0xffffffffu, w, j);
            int sj = __shfl_sync(0xffffffffu, s, j);
            float4 hv = ((const float4*)(g_h + (size_t)sj * HH))[lane];
            acc.x += wj * hv.x; acc.y += wj * hv.y;
            acc.z += wj * hv.z; acc.w += wj * hv.w;
        }
    }
    float wl = __expf(aloop - m);
    {
        float4 hv = ((const float4*)(g_h + (size_t)v * HH))[lane];
        acc.x += wl * hv.x; acc.y += wl * hv.y;
        acc.z += wl * hv.z; acc.w += wl * hv.w;
    }
    float inv = 1.f / (warpSum(dsum) + wl);
    float4 b4 = ((const float4*)bias)[lane];
    float4 o;
    o.x = acc.x * inv + b4.x; o.y = acc.y * inv + b4.y;
    o.z = acc.z * inv + b4.z; o.w = acc.w * inv + b4.w;
    if (!layer2) {
        o.x = fmaxf(o.x, 0.f); o.y = fmaxf(o.y, 0.f);
        o.z = fmaxf(o.z, 0.f); o.w = fmaxf(o.w, 0.f);
        // fused bf16 split for layer-2 GEMM input (row stride HH)
        __nv_bfloat16 h0, h1, h2, h3, m0, m1, m2, m3;
        split1(o.x, h0, m0); split1(o.y, h1, m1);
        split1(o.z, h2, m2); split1(o.w, h3, m3);
        __nv_bfloat162* pAh = (__nv_bfloat162*)(g_Ah + (size_t)v * HH) + lane * 2;
        __nv_bfloat162* pAm = (__nv_bfloat162*)(g_Am + (size_t)v * HH) + lane * 2;
        pAh[0] = __nv_bfloat162(h0, h1); pAh[1] = __nv_bfloat162(h2, h3);
        pAm[0] = __nv_bfloat162(m0, m1); pAm[1] = __nv_bfloat162(m2, m3);
    }
    ((float4*)(g_out + (size_t)v * HH))[lane] = o;
}

// ------------------------- decode (direct atomic fold into out) --------------
__global__ __launch_bounds__(256)
void k_decode_csr(float* __restrict__ out, int half, int n) {
    int warp = (blockIdx.x * blockDim.x + threadIdx.x) >> 5;
    int lane = threadIdx.x & 31;
    if (warp >= n) return;
    int v = warp;
    int r0 = g_rowptr[v], r1 = g_rowptr[v + 1];
    float4 zd = ((const float4*)(g_out + (size_t)v * HH))[lane];
    int i = r0;
    for (; i + 2 <= r1; i += 2) {
        EdgeRec ra = g_rec[i], rb = g_rec[i + 1];
        float4 z0 = ((const float4*)(g_out + (size_t)ra.src * HH))[lane];
        float4 z1 = ((const float4*)(g_out + (size_t)rb.src * HH))[lane];
        float p0 = zd.x * z0.x + zd.y * z0.y + zd.z * z0.z + zd.w * z0.w;
        float p1 = zd.x * z1.x + zd.y * z1.y + zd.z * z1.z + zd.w * z1.w;
#pragma unroll
        for (int o = 16; o; o >>= 1) {
            p0 += __shfl_xor_sync(0xffffffffu, p0, o);
            p1 += __shfl_xor_sync(0xffffffffu, p1, o);
        }
        if (lane == 0) {
            int o0 = ra.eid >= half ? ra.eid - half : ra.eid;
            int o1 = rb.eid >= half ? rb.eid - half : rb.eid;
            atomicAdd(&out[o0], p0);
            atomicAdd(&out[o1], p1);
        }
    }
    if (i < r1) {
        EdgeRec ra = g_rec[i];
        float4 z0 = ((const float4*)(g_out + (size_t)ra.src * HH))[lane];
        float p0 = zd.x * z0.x + zd.y * z0.y + zd.z * z0.z + zd.w * z0.w;
        p0 = warpSum(p0);
        if (lane == 0) {
            int o0 = ra.eid >= half ? ra.eid - half : ra.eid;
            atomicAdd(&out[o0], p0);
        }
    }
}

// ------------------------- launch --------------------------------------------
extern "C" void kernel_launch(void* const* d_in, const int* in_sizes, int n_in,
                              void* d_out, int out_size) {
    const float* x   = (const float*)d_in[0];
    const int*   ei  = (const int*)d_in[1];
    const float* ef  = (const float*)d_in[2];
    const float* W1  = (const float*)d_in[4];
    const float* as1 = (const float*)d_in[5];
    const float* ad1 = (const float*)d_in[6];
    const float* We1 = (const float*)d_in[7];
    const float* ae1 = (const float*)d_in[8];
    const float* b1  = (const float*)d_in[9];
    const float* W2  = (const float*)d_in[10];
    const float* as2 = (const float*)d_in[11];
    const float* ad2 = (const float*)d_in[12];
    const float* We2 = (const float*)d_in[13];
    const float* ae2 = (const float*)d_in[14];
    const float* b2  = (const float*)d_in[15];

    const int E = in_sizes[1] / 2;
    const int N = in_sizes[0] / FIN;
    const int* src = ei;
    const int* dst = ei + E;
    const int half = E / 2;

    cudaFuncSetAttribute(k_gemm, cudaFuncAttributeMaxDynamicSharedMemorySize, GEMM_SMEM);
    cudaFuncSetAttribute(k_edge_ae, cudaFuncAttributeMaxDynamicSharedMemorySize, EA_SMEM);

    // CSR + edge preprocessing
    k_zero<<<(N + 255) / 256, 256>>>(N);
    k_zero_out<<<(half + 255) / 256, 256>>>((float*)d_out, half);
    k_we2<<<16, 256>>>(We1, ae1, We2, ae2);
    k_edge_ae<<<E / 256, 256, EA_SMEM>>>(ef, dst, E);
    k_scan1<<<(N + 1023) / 1024, 1024>>>(N);
    k_scan2<<<1, 64>>>((N + 1023) / 1024);
    k_scan3<<<(N + 255) / 256, 256>>>(N);
    k_fill<<<(E + 255) / 256, 256>>>(src, dst, E);

    // layer 1
    k_splitW<<<(128 * FIN + 255) / 256, 256>>>(W1, FIN);
    k_splitA<<<((N * FIN / 4) + 255) / 256, 256>>>(x, N * FIN / 4);
    k_gemm<<<(N + 127) / 128, 256, GEMM_SMEM>>>(as1, ad1, N, FIN);
    k_aggregate<<<(N * 32 + 255) / 256, 256>>>(b1, N, 0);

    // layer 2 (split of layer-1 output fused into k_aggregate)
    k_splitW<<<(128 * HH + 255) / 256, 256>>>(W2, HH);
    k_gemm<<<(N + 127) / 128, 256, GEMM_SMEM>>>(as2, ad2, N, HH);
    k_aggregate<<<(N * 32 + 255) / 256, 256>>>(b2, N, 1);

    // decode
    k_decode_csr<<<(N * 32 + 255) / 256, 256>>>((float*)d_out, half, N);
}